// round 14
// baseline (speedup 1.0000x reference)
#include <cuda_runtime.h>
#include <cuda_bf16.h>
#include <cstdint>
#include <math.h>

// ---------------- problem constants ----------------
#define Bq   2
#define Cc   128
#define Hf   256
#define Wf   256
#define Nf   (Hf*Wf)      // 65536
#define Hh   128
#define Wh   128
#define Nh2  (Hh*Wh)      // 16384
#define NHh  8
#define HD   16

#define HB   ((size_t)Bq*Cc*Nh2)

// ---------------- device scratch ----------------
__device__ float g_qkv [(size_t)Bq*3*Cc*Nf];
__device__ float g_qkvd[(size_t)Bq*3*Cc*Nf];
__device__ float g_hbuf[10*((size_t)Bq*Cc*Nh2)];
__device__ float g_masks[(size_t)Bq*5*Cc*Nh2];
__device__ float g_qcat [(size_t)Bq*2*Cc*Nh2];
__device__ float g_gram [Bq*NHh*288];
__device__ float g_weff [Bq*Cc*Cc];

__device__ __forceinline__ float sigm(float v) { return 1.f/(1.f+__expf(-v)); }

// =====================================================================
// tf32 helpers
// =====================================================================
__device__ __forceinline__ uint32_t f2tf32(float f) {
    uint32_t r;
    asm("cvt.rna.tf32.f32 %0, %1;" : "=r"(r) : "f"(f));
    return r;
}
__device__ __forceinline__ void mma_tf32(float c[4], const uint32_t a[4], const uint32_t b[2]) {
    asm volatile(
        "mma.sync.aligned.m16n8k8.row.col.f32.tf32.tf32.f32 "
        "{%0,%1,%2,%3}, {%4,%5,%6,%7}, {%8,%9}, {%0,%1,%2,%3};"
        : "+f"(c[0]), "+f"(c[1]), "+f"(c[2]), "+f"(c[3])
        : "r"(a[0]), "r"(a[1]), "r"(a[2]), "r"(a[3]), "r"(b[0]), "r"(b[1]));
}

// =====================================================================
// conv1x1 tf32 GEMM — double-buffered A&B, one sync per 32-K stage (R11)
// =====================================================================
#define A_STR 36
#define B_STR 132
#define AWRD (128*A_STR)
#define BWRD (32*B_STR)
#define CONV_SMEM ((2*AWRD + 2*BWRD)*4)   // 70656 bytes

template<int EPI>
__global__ void __launch_bounds__(256, 2) conv1x1_mma(
    const float* __restrict__ in, const float* __restrict__ w,
    const float* __restrict__ bias, float* __restrict__ out,
    const float* __restrict__ mask,
    int Cin, int P,
    size_t inBS, size_t outBS, size_t wBS, size_t maskBS)
{
    extern __shared__ uint32_t sdyn[];
    uint32_t* const Asb[2] = { sdyn, sdyn + AWRD };
    uint32_t* const Bsb[2] = { sdyn + 2*AWRD, sdyn + 2*AWRD + BWRD };

    const int b = blockIdx.z;
    in  += (size_t)b * inBS;
    out += (size_t)b * outBS;
    w   += (size_t)b * wBS;
    if (EPI == 2) mask += (size_t)b * maskBS;

    const int p0 = blockIdx.x * 128;
    const int o0 = blockIdx.y * 128;

    const int t = threadIdx.x;
    const int lane = t & 31;
    const int wrp  = t >> 5;
    const int wm   = wrp & 3;
    const int wn   = wrp >> 2;
    const int gid  = lane >> 2;
    const int tig  = lane & 3;

    int aOff[4], bOff[4];
#pragma unroll
    for (int i = 0; i < 4; i++) {
        const int slot = t + i * 256;
        aOff[i] = (slot >> 3) * A_STR + (slot & 7) * 4;
        bOff[i] = (slot >> 5) * B_STR + (slot & 31) * 4;
    }

    float acc[2][8][4];
#pragma unroll
    for (int i = 0; i < 2; i++)
#pragma unroll
        for (int j = 0; j < 8; j++)
#pragma unroll
            for (int r = 0; r < 4; r++) acc[i][j][r] = 0.f;

    const int nStages = Cin >> 5;

    float4 aPre[4], bPre[4];
    auto loadStage = [&](int s) {
        const float* wb = w + (size_t)o0 * Cin + (s << 5);
        const float* ib = in + (size_t)(s << 5) * P + p0;
#pragma unroll
        for (int i = 0; i < 4; i++) {
            const int slot = t + i * 256;
            aPre[i] = *(const float4*)(wb + (size_t)(slot >> 3) * Cin + (slot & 7) * 4);
            bPre[i] = *(const float4*)(ib + (size_t)(slot >> 5) * P + (slot & 31) * 4);
        }
    };
    auto stsStage = [&](int buf) {
        uint32_t* As = Asb[buf];
        uint32_t* Bs = Bsb[buf];
#pragma unroll
        for (int i = 0; i < 4; i++) {
            uint4 ua, ub;
            ua.x = f2tf32(aPre[i].x); ua.y = f2tf32(aPre[i].y);
            ua.z = f2tf32(aPre[i].z); ua.w = f2tf32(aPre[i].w);
            ub.x = f2tf32(bPre[i].x); ub.y = f2tf32(bPre[i].y);
            ub.z = f2tf32(bPre[i].z); ub.w = f2tf32(bPre[i].w);
            *(uint4*)(As + aOff[i]) = ua;
            *(uint4*)(Bs + bOff[i]) = ub;
        }
    };

    loadStage(0);
    stsStage(0);

    for (int stage = 0; stage < nStages; stage++) {
        const int buf = stage & 1;
        if (stage + 1 < nStages) loadStage(stage + 1);
        __syncthreads();

        const uint32_t* As = Asb[buf];
        const uint32_t* Bs = Bsb[buf];
#pragma unroll
        for (int k0 = 0; k0 < 32; k0 += 8) {
            uint32_t af[2][4];
#pragma unroll
            for (int tm = 0; tm < 2; tm++) {
                const int rb = wm * 32 + tm * 16;
                af[tm][0] = As[(rb + gid    ) * A_STR + k0 + tig    ];
                af[tm][1] = As[(rb + gid + 8) * A_STR + k0 + tig    ];
                af[tm][2] = As[(rb + gid    ) * A_STR + k0 + tig + 4];
                af[tm][3] = As[(rb + gid + 8) * A_STR + k0 + tig + 4];
            }
#pragma unroll
            for (int tn = 0; tn < 8; tn++) {
                uint32_t bf[2];
                const int col = wn * 64 + tn * 8 + gid;
                bf[0] = Bs[(k0 + tig    ) * B_STR + col];
                bf[1] = Bs[(k0 + tig + 4) * B_STR + col];
#pragma unroll
                for (int tm = 0; tm < 2; tm++)
                    mma_tf32(acc[tm][tn], af[tm], bf);
            }
        }
        if (stage + 1 < nStages) stsStage((stage + 1) & 1);
    }

#pragma unroll
    for (int tm = 0; tm < 2; tm++) {
        const int oA = o0 + wm * 32 + tm * 16 + gid;
        const int oB = oA + 8;
        const float bvA = __ldg(bias + oA);
        const float bvB = __ldg(bias + oB);
#pragma unroll
        for (int tn = 0; tn < 8; tn++) {
            const int p = p0 + wn * 64 + tn * 8 + tig * 2;
            float v0 = acc[tm][tn][0] + bvA;
            float v1 = acc[tm][tn][1] + bvA;
            float v2 = acc[tm][tn][2] + bvB;
            float v3 = acc[tm][tn][3] + bvB;
            if (EPI == 1) {
                v0 = sigm(v0); v1 = sigm(v1); v2 = sigm(v2); v3 = sigm(v3);
            }
            if (EPI == 2) {
                const float2 iA = *(const float2*)(in + (size_t)oA * P + p);
                const float2 iB = *(const float2*)(in + (size_t)oB * P + p);
                const float2 mA = *(const float2*)(mask + (size_t)oA * P + p);
                const float2 mB = *(const float2*)(mask + (size_t)oB * P + p);
                v0 = iA.x + v0 * mA.x; v1 = iA.y + v1 * mA.y;
                v2 = iB.x + v2 * mB.x; v3 = iB.y + v3 * mB.y;
            }
            *(float2*)(out + (size_t)oA * P + p) = make_float2(v0, v1);
            *(float2*)(out + (size_t)oB * P + p) = make_float2(v2, v3);
        }
    }
}

// =====================================================================
// depthwise 3x3 on k,v channels — float4 row loads
// =====================================================================
__global__ void __launch_bounds__(256) dwconv3_k(
    const float* __restrict__ in, const float* __restrict__ wk,
    const float* __restrict__ wv, float* __restrict__ out)
{
    const int zc2 = blockIdx.z;
    const int b   = zc2 / (2*Cc);
    const int ch2 = zc2 % (2*Cc);
    const int cm  = ch2 % Cc;
    const float* ws = (ch2 < Cc) ? wk : wv;
    float wgt[9];
#pragma unroll
    for (int i=0;i<9;i++) wgt[i] = __ldg(ws + cm*9 + i);

    const size_t off = ((size_t)b*3*Cc + Cc + ch2)*Nf;
    const float* ip = in  + off;
    float*       op = out + off;

    const int x0 = (blockIdx.x*32 + threadIdx.x)*4;
    const int y  = blockIdx.y*8  + threadIdx.y;

    float r[3][6];
#pragma unroll
    for (int dy=0; dy<3; dy++) {
        const int yy = y + dy - 1;
        const bool rv = (unsigned)yy < (unsigned)Hf;
        const float* rp = ip + (size_t)yy*Wf;
        if (rv) {
            const float4 m = *(const float4*)(rp + x0);
            r[dy][1]=m.x; r[dy][2]=m.y; r[dy][3]=m.z; r[dy][4]=m.w;
            r[dy][0] = (x0 > 0)      ? __ldg(rp + x0 - 1) : 0.f;
            r[dy][5] = (x0 + 4 < Wf) ? __ldg(rp + x0 + 4) : 0.f;
        } else {
#pragma unroll
            for (int j=0;j<6;j++) r[dy][j] = 0.f;
        }
    }
    float o[4] = {0.f,0.f,0.f,0.f};
#pragma unroll
    for (int dy=0; dy<3; dy++)
#pragma unroll
        for (int dx=0; dx<3; dx++) {
            const float wv_ = wgt[dy*3+dx];
#pragma unroll
            for (int j=0; j<4; j++) o[j] = fmaf(r[dy][j+dx], wv_, o[j]);
        }
    *(float4*)(op + (size_t)y*Wf + x0) = make_float4(o[0],o[1],o[2],o[3]);
}

// =====================================================================
// fused dwconv3(q) + Haar DWT — 2 half-px/thread, float4 row loads
// =====================================================================
__global__ void __launch_bounds__(256) dwconv_dwt_k(
    const float* __restrict__ in, const float* __restrict__ wq,
    float* __restrict__ ll, float* __restrict__ lh,
    float* __restrict__ hl, float* __restrict__ hh)
{
    const int zc = blockIdx.z;               // b*C + ch
    const int b = zc / Cc, ch = zc % Cc;
    float wgt[9];
#pragma unroll
    for (int i=0;i<9;i++) wgt[i] = __ldg(wq + ch*9 + i);

    const float* ip = in + ((size_t)b*3*Cc + ch)*Nf;
    const size_t ho = (size_t)zc*Nh2;

    const int xq = blockIdx.x*32 + threadIdx.x;
    const int yh = blockIdx.y*8  + threadIdx.y;
    const int fx = xq*4;

    float r[4][6];
#pragma unroll
    for (int dy=0; dy<4; dy++) {
        const int yy = 2*yh + dy - 1;
        const bool rv = (unsigned)yy < (unsigned)Hf;
        const float* rp = ip + (size_t)yy*Wf;
        if (rv) {
            const float4 m = *(const float4*)(rp + fx);
            r[dy][1]=m.x; r[dy][2]=m.y; r[dy][3]=m.z; r[dy][4]=m.w;
            r[dy][0] = (fx > 0)      ? __ldg(rp + fx - 1) : 0.f;
            r[dy][5] = (fx + 4 < Wf) ? __ldg(rp + fx + 4) : 0.f;
        } else {
#pragma unroll
            for (int j=0;j<6;j++) r[dy][j] = 0.f;
        }
    }
    float o[2][4];
#pragma unroll
    for (int qy=0; qy<2; qy++)
#pragma unroll
        for (int k=0; k<4; k++) {
            float s = 0.f;
#pragma unroll
            for (int ky=0; ky<3; ky++)
#pragma unroll
                for (int kx=0; kx<3; kx++)
                    s = fmaf(r[qy+ky][k+kx], wgt[ky*3+kx], s);
            o[qy][k] = s;
        }
    const size_t p = ho + (size_t)yh*Wh + xq*2;
    float2 vll, vlh, vhl, vhh;
    {
        const float a=o[0][0], bb2=o[0][1], c=o[1][0], d=o[1][1];
        vll.x=(a+bb2+c+d)*0.5f; vlh.x=(a+bb2-c-d)*0.5f;
        vhl.x=(a-bb2+c-d)*0.5f; vhh.x=(a-bb2-c+d)*0.5f;
    }
    {
        const float a=o[0][2], bb2=o[0][3], c=o[1][2], d=o[1][3];
        vll.y=(a+bb2+c+d)*0.5f; vlh.y=(a+bb2-c-d)*0.5f;
        vhl.y=(a-bb2+c-d)*0.5f; vhh.y=(a-bb2-c+d)*0.5f;
    }
    *(float2*)(ll+p) = vll;
    *(float2*)(lh+p) = vlh;
    *(float2*)(hl+p) = vhl;
    *(float2*)(hh+p) = vhh;
}

// =====================================================================
// smem-tiled single-stage gated conv + mask premultiply
// =====================================================================
template<int KH,int KW>
__global__ void __launch_bounds__(256) gated_s(
    const float* __restrict__ in, const float* __restrict__ w,
    const float* __restrict__ masks, int bandOff,
    float* __restrict__ out)
{
    constexpr int HALO_Y = KH/2, HALO_X = KW/2;
    constexpr int TR = 8 + KH - 1;
    constexpr int TC = 128 + KW - 1;
    __shared__ float sm[TR][TC];
    __shared__ float wsm[2][KH*KW];

    const int zc = blockIdx.z;
    const int b  = zc / Cc;
    const int ch = zc % Cc;
    const int t  = threadIdx.y*32 + threadIdx.x;
    if (t < 2*KH*KW) {
        const int br = t / (KH*KW), i = t % (KH*KW);
        wsm[br][i] = __ldg(w + (size_t)br*Cc*KH*KW + (size_t)ch*KH*KW + i);
    }

    const float* ip = in + (size_t)zc*Nh2;
    const float* mp = masks + ((size_t)b*5*Cc + bandOff + ch)*Nh2;
    const int Y0 = blockIdx.y*8;

    for (int idx = t; idx < TR*TC; idx += 256) {
        const int r = idx / TC, c = idx % TC;
        const int gy = Y0 - HALO_Y + r, gx = c - HALO_X;
        sm[r][c] = ((unsigned)gy < (unsigned)Hh && (unsigned)gx < (unsigned)Wh)
                   ? __ldg(ip + (size_t)gy*Wh + gx) : 0.f;
    }
    __syncthreads();

    const int ty = threadIdx.y;
    const int x0 = threadIdx.x*4;
    float s0[4] = {0,0,0,0}, s1[4] = {0,0,0,0};
#pragma unroll
    for (int ky=0; ky<KH; ky++) {
        float row[KW+3];
#pragma unroll
        for (int j=0; j<KW+3; j++) row[j] = sm[ty+ky][x0+j];
#pragma unroll
        for (int kx=0; kx<KW; kx++) {
            const float a0 = wsm[0][ky*KW+kx], a1 = wsm[1][ky*KW+kx];
#pragma unroll
            for (int j=0; j<4; j++) {
                s0[j] = fmaf(row[j+kx], a0, s0[j]);
                s1[j] = fmaf(row[j+kx], a1, s1[j]);
            }
        }
    }
    const float4 mv = *(const float4*)(mp + (size_t)(Y0+ty)*Wh + x0);
    float4 o;
    o.x = s0[0]*sigm(s1[0])*mv.x; o.y = s0[1]*sigm(s1[1])*mv.y;
    o.z = s0[2]*sigm(s1[2])*mv.z; o.w = s0[3]*sigm(s1[3])*mv.w;
    *(float4*)(out + (size_t)zc*Nh2 + (size_t)(Y0+ty)*Wh + x0) = o;
}

// =====================================================================
// fused dual 2-stage gated chains, occupancy-capped regs
// =====================================================================
__global__ void __launch_bounds__(256, 5) gated2_dual_k(
    const float* __restrict__ in,
    const float* __restrict__ wA, const float* __restrict__ wB,
    float* __restrict__ outA, float* __restrict__ outB)
{
    __shared__ float sm[12][132];
    __shared__ float midA[10][132];
    __shared__ float midB[10][132];
    __shared__ float wsm[8][9];

    const int zc = blockIdx.z;
    const int ch = zc % Cc;
    const int t  = threadIdx.y*32 + threadIdx.x;

    if (t < 72) {
        const int set = t / 9, i = t % 9;
        const float* base = (set < 4) ? wA : wB;
        const int s4 = set & 3;
        wsm[set][i] = __ldg(base + (size_t)s4*Cc*9 + (size_t)ch*9 + i);
    }

    const float* ip = in + (size_t)zc*Nh2;
    const int Y0 = blockIdx.y*8;

    for (int idx = t; idx < 12*132; idx += 256) {
        const int r = idx / 132, c = idx % 132;
        const int gy = Y0 - 2 + r, gx = c - 2;
        sm[r][c] = ((unsigned)gy < (unsigned)Hh && (unsigned)gx < (unsigned)Wh)
                   ? __ldg(ip + (size_t)gy*Wh + gx) : 0.f;
    }
    __syncthreads();

    for (int idx = t; idx < 10*130; idx += 256) {
        const int r = idx / 130, c = idx % 130;
        const int gy = Y0 - 1 + r, gx = c - 1;
        float a0=0, a1=0, b0=0, b1=0;
        if ((unsigned)gy < (unsigned)Hh && (unsigned)gx < (unsigned)Wh) {
#pragma unroll
            for (int ky=0; ky<3; ky++)
#pragma unroll
                for (int kx=0; kx<3; kx++) {
                    const float v = sm[r+ky][c+kx];
                    const int i = ky*3+kx;
                    a0 = fmaf(v, wsm[0][i], a0);
                    a1 = fmaf(v, wsm[1][i], a1);
                    b0 = fmaf(v, wsm[4][i], b0);
                    b1 = fmaf(v, wsm[5][i], b1);
                }
        }
        midA[r][c] = a0 * sigm(a1);
        midB[r][c] = b0 * sigm(b1);
    }
    __syncthreads();

    const int ty = threadIdx.y;
    const int x0 = threadIdx.x*4;
    float sA0[4]={0,0,0,0}, sA1[4]={0,0,0,0}, sB0[4]={0,0,0,0}, sB1[4]={0,0,0,0};
#pragma unroll
    for (int ky=0; ky<3; ky++) {
        float rA[6], rB[6];
#pragma unroll
        for (int j=0; j<6; j++) { rA[j] = midA[ty+ky][x0+j]; rB[j] = midB[ty+ky][x0+j]; }
#pragma unroll
        for (int kx=0; kx<3; kx++) {
            const int i = ky*3+kx;
            const float a2_0 = wsm[2][i], a2_1 = wsm[3][i];
            const float b2_0 = wsm[6][i], b2_1 = wsm[7][i];
#pragma unroll
            for (int j=0; j<4; j++) {
                sA0[j] = fmaf(rA[j+kx], a2_0, sA0[j]);
                sA1[j] = fmaf(rA[j+kx], a2_1, sA1[j]);
                sB0[j] = fmaf(rB[j+kx], b2_0, sB0[j]);
                sB1[j] = fmaf(rB[j+kx], b2_1, sB1[j]);
            }
        }
    }
    const size_t op = (size_t)zc*Nh2 + (size_t)(Y0+ty)*Wh + x0;
    float4 oA, oB;
    oA.x = sA0[0]*sigm(sA1[0]); oA.y = sA0[1]*sigm(sA1[1]);
    oA.z = sA0[2]*sigm(sA1[2]); oA.w = sA0[3]*sigm(sA1[3]);
    oB.x = sB0[0]*sigm(sB1[0]); oB.y = sB0[1]*sigm(sB1[1]);
    oB.z = sB0[2]*sigm(sB1[2]); oB.w = sB0[3]*sigm(sB1[3]);
    *(float4*)(outA + op) = oA;
    *(float4*)(outB + op) = oB;
}

// =====================================================================
// fused IDWT + gram
// =====================================================================
#define G2_T 8
#define QS_STR 260
__global__ void __launch_bounds__(256) gram2_k(
    const float* __restrict__ ll, const float* __restrict__ lh,
    const float* __restrict__ hl, const float* __restrict__ hh,
    const float* __restrict__ kall, float* __restrict__ gram)
{
    const int h = blockIdx.y, b = blockIdx.z;
    const size_t cb = ((size_t)b*Cc + h*HD)*Nh2;
    const float* llb = ll + cb;
    const float* lhb = lh + cb;
    const float* hlb = hl + cb;
    const float* hhb = hh + cb;
    const float* kb  = kall + (size_t)b*3*Cc*Nf + (size_t)Cc*Nf + (size_t)h*HD*Nf;

    __shared__ float qs[16][QS_STR];
    __shared__ float ks[16][QS_STR];

    const int t = threadIdx.x;
    const int i = t >> 4, j = t & 15;
    float accS = 0.f, accQ = 0.f, accK = 0.f;

    for (int tt = 0; tt < G2_T; tt++) {
        const int tileId = blockIdx.x * G2_T + tt;
        const int yh  = tileId >> 1;
        const int xh0 = (tileId & 1) * 64;

#pragma unroll
        for (int e = 0; e < 4; e++) {
            const int idx = t + e*256;
            const int r = idx >> 6, xl = idx & 63;
            const size_t p = (size_t)r*Nh2 + (size_t)yh*Wh + xh0 + xl;
            const float vll = llb[p], vlh = lhb[p], vhl = hlb[p], vhh = hhb[p];
            const int xc = xl*2;
            qs[r][xc      ] = (vll+vlh+vhl+vhh)*0.5f;
            qs[r][xc+1    ] = (vll+vlh-vhl-vhh)*0.5f;
            qs[r][128+xc  ] = (vll-vlh+vhl-vhh)*0.5f;
            qs[r][128+xc+1] = (vll-vlh-vhl+vhh)*0.5f;
        }
        const size_t n0 = (size_t)(2*yh)*Wf + 2*xh0;
#pragma unroll
        for (int e = 0; e < 4; e++) {
            const int idx = t + e*256;
            const int r = idx >> 6, rem = idx & 63;
            const int row = rem >> 5, c4 = rem & 31;
            const float4 v = *(const float4*)(kb + (size_t)r*Nf + n0 + row*Wf + c4*4);
            *(float4*)&ks[r][row*128 + c4*4] = v;
        }
        __syncthreads();
#pragma unroll 8
        for (int nn = 0; nn < 256; nn++) {
            const float qv = qs[i][nn];
            const float kv = ks[j][nn];
            accS = fmaf(qv, kv, accS);
            if (j == 0) accQ = fmaf(qv, qv, accQ);
            if (i == 0) accK = fmaf(kv, kv, accK);
        }
        __syncthreads();
    }
    float* gp = gram + (size_t)(b*NHh + h)*288;
    atomicAdd(gp + i*16 + j, accS);
    if (j == 0) atomicAdd(gp + 256 + i, accQ);
    if (i == 0) atomicAdd(gp + 272 + j, accK);
}

// =====================================================================
// softmax + fold w_out
// =====================================================================
__global__ void attw_k(const float* __restrict__ gram,
                       const float* __restrict__ temp,
                       const float* __restrict__ wout,
                       float* __restrict__ weff)
{
    const int b = blockIdx.x;
    __shared__ float att[NHh][16][16];
    const int t = threadIdx.x;
    const float* gb = gram + (size_t)b*NHh*288;

    if (t < 128) {
        const int h = t >> 4, i = t & 15;
        const float* gp = gb + h*288;
        const float nq = fmaxf(sqrtf(gp[256+i]), 1e-12f);
        const float tv = temp[h];
        float logit[16];
        float mx = -1e30f;
#pragma unroll
        for (int j=0;j<16;j++) {
            const float nk = fmaxf(sqrtf(gp[272+j]), 1e-12f);
            const float l = gp[i*16+j] / (nq*nk) * tv;
            logit[j] = l;
            mx = fmaxf(mx, l);
        }
        float se = 0.f;
#pragma unroll
        for (int j=0;j<16;j++) { const float e = __expf(logit[j]-mx); logit[j]=e; se+=e; }
        const float inv = 1.f/se;
#pragma unroll
        for (int j=0;j<16;j++) att[h][i][j] = logit[j]*inv;
    }
    __syncthreads();

    float* wb = weff + (size_t)b*Cc*Cc;
    for (int idx = t; idx < Cc*Cc; idx += 256) {
        const int o = idx >> 7, cp = idx & 127;
        const int h = cp >> 4, j = cp & 15;
        float s = 0.f;
#pragma unroll
        for (int i=0;i<16;i++)
            s = fmaf(wout[(size_t)o*Cc + h*16 + i], att[h][i][j], s);
        wb[idx] = s;
    }
}

// =====================================================================
// host launch — q/kv GEMM split for pipe-complementary overlap
// =====================================================================
extern "C" void kernel_launch(void* const* d_in, const int* in_sizes, int n_in,
                              void* d_out, int out_size)
{
    const float* x      = (const float*)d_in[0];
    const float* prior  = (const float*)d_in[1];
    const float* w_lin  = (const float*)d_in[2];
    const float* b_lin  = (const float*)d_in[3];
    const float* w_qd   = (const float*)d_in[4];
    const float* w_kd   = (const float*)d_in[5];
    const float* w_vd   = (const float*)d_in[6];
    const float* gw_llr = (const float*)d_in[7];
    const float* gw_llh = (const float*)d_in[8];
    const float* gw_lh  = (const float*)d_in[9];
    const float* gw_hl  = (const float*)d_in[10];
    const float* gw_hh  = (const float*)d_in[11];
    const float* w_prior= (const float*)d_in[12];
    const float* b_prior= (const float*)d_in[13];
    const float* w_pw1  = (const float*)d_in[14];
    const float* b_pw1  = (const float*)d_in[15];
    const float* w_pw2  = (const float*)d_in[16];
    const float* b_pw2  = (const float*)d_in[17];
    const float* w_cat  = (const float*)d_in[18];
    const float* b_cat  = (const float*)d_in[19];
    const float* temper = (const float*)d_in[20];
    const float* w_out  = (const float*)d_in[21];
    const float* b_out  = (const float*)d_in[22];

    float *qkv, *qkvd, *hbuf, *masks, *qcat, *gram, *weff;
    cudaGetSymbolAddress((void**)&qkv,   g_qkv);
    cudaGetSymbolAddress((void**)&qkvd,  g_qkvd);
    cudaGetSymbolAddress((void**)&hbuf,  g_hbuf);
    cudaGetSymbolAddress((void**)&masks, g_masks);
    cudaGetSymbolAddress((void**)&qcat,  g_qcat);
    cudaGetSymbolAddress((void**)&gram,  g_gram);
    cudaGetSymbolAddress((void**)&weff,  g_weff);

    static cudaStream_t s1 = nullptr, s2 = nullptr;
    static cudaEvent_t eStart = nullptr, eQ = nullptr, eKV = nullptr,
                       eM = nullptr, eDWT = nullptr, eG = nullptr,
                       eDual = nullptr, ePw2 = nullptr;
    if (s1 == nullptr) {
        cudaStreamCreateWithFlags(&s1, cudaStreamNonBlocking);
        cudaStreamCreateWithFlags(&s2, cudaStreamNonBlocking);
        cudaEventCreateWithFlags(&eStart, cudaEventDisableTiming);
        cudaEventCreateWithFlags(&eQ,     cudaEventDisableTiming);
        cudaEventCreateWithFlags(&eKV,    cudaEventDisableTiming);
        cudaEventCreateWithFlags(&eM,     cudaEventDisableTiming);
        cudaEventCreateWithFlags(&eDWT,   cudaEventDisableTiming);
        cudaEventCreateWithFlags(&eG,     cudaEventDisableTiming);
        cudaEventCreateWithFlags(&eDual,  cudaEventDisableTiming);
        cudaEventCreateWithFlags(&ePw2,   cudaEventDisableTiming);
        cudaFuncSetAttribute(conv1x1_mma<0>, cudaFuncAttributeMaxDynamicSharedMemorySize, CONV_SMEM);
        cudaFuncSetAttribute(conv1x1_mma<1>, cudaFuncAttributeMaxDynamicSharedMemorySize, CONV_SMEM);
        cudaFuncSetAttribute(conv1x1_mma<2>, cudaFuncAttributeMaxDynamicSharedMemorySize, CONV_SMEM);
    }

    float* ll   = hbuf + 0*HB;
    float* lh   = hbuf + 1*HB;
    float* hl   = hbuf + 2*HB;
    float* hh   = hbuf + 3*HB;
    float* llrg = hbuf + 5*HB;
    float* llhg = hbuf + 6*HB;
    float* lhg  = hbuf + 7*HB;
    float* hlg  = hbuf + 8*HB;
    float* hhg  = hbuf + 9*HB;

    const size_t fullBS = (size_t)Cc*Nf;
    const size_t qkvBS  = (size_t)3*Cc*Nf;
    const size_t halfBS = (size_t)Cc*Nh2;
    const size_t mBS    = (size_t)5*Cc*Nh2;
    const size_t catBS  = (size_t)2*Cc*Nh2;

    const size_t xel = (size_t)in_sizes[0];
    const size_t pel = (size_t)in_sizes[1];

    // fork side streams
    cudaEventRecord(eStart, 0);
    cudaStreamWaitEvent(s2, eStart, 0);
    cudaStreamWaitEvent(s1, eStart, 0);

    // s1: independent setup
    if ((size_t)out_size >= xel + pel) {
        cudaMemcpyAsync((float*)d_out + xel, prior, pel*sizeof(float),
                        cudaMemcpyDeviceToDevice, s1);
    }
    cudaMemsetAsync(gram, 0, (size_t)Bq*NHh*288*sizeof(float), s1);

    // s2: masks = sigmoid(conv1x1(prior))
    conv1x1_mma<1><<<dim3(Nh2/128, 5, Bq), 256, CONV_SMEM, s2>>>(
        prior, w_prior, b_prior, masks, nullptr, Cc, Nh2, halfBS, mBS, 0, 0);
    cudaEventRecord(eM, s2);

    // 0: q-only GEMM (channels 0..127) — the q-branch gate
    conv1x1_mma<0><<<dim3(Nf/128, 1, Bq), 256, CONV_SMEM>>>(
        x, w_lin, b_lin, qkv, nullptr, Cc, Nf, fullBS, qkvBS, 0, 0);
    cudaEventRecord(eQ, 0);

    // s1: k,v GEMM (channels 128..383) + depthwise 3x3(k,v) — overlaps entire q-branch
    cudaStreamWaitEvent(s1, eQ, 0);
    conv1x1_mma<0><<<dim3(Nf/128, 2, Bq), 256, CONV_SMEM, s1>>>(
        x, w_lin + (size_t)Cc*Cc, b_lin + Cc, qkv + (size_t)Cc*Nf, nullptr,
        Cc, Nf, fullBS, qkvBS, 0, 0);
    dwconv3_k<<<dim3(Wf/128, Hf/8, Bq*2*Cc), dim3(32,8), 0, s1>>>(qkv, w_kd, w_vd, qkvd);
    cudaEventRecord(eKV, s1);

    // 0: q-branch — fused dwconv(q)+DWT
    dwconv_dwt_k<<<dim3(2, Hh/8, Bq*Cc), dim3(32,8)>>>(qkv, w_qd, ll, lh, hl, hh);
    cudaEventRecord(eDWT, 0);

    dim3 gg(1, Hh/8, Bq*Cc), bg(32,8);

    // s2: single-stage gated convs with mask premultiply (masks already on s2)
    cudaStreamWaitEvent(s2, eDWT, 0);
    gated_s<3,5><<<gg, bg, 0, s2>>>(lh, gw_lh, masks, 1*Cc, lhg);
    gated_s<5,3><<<gg, bg, 0, s2>>>(hl, gw_hl, masks, 2*Cc, hlg);
    gated_s<3,3><<<gg, bg, 0, s2>>>(hh, gw_hh, masks, 3*Cc, hhg);
    cudaEventRecord(eG, s2);

    // 0: dual gated chain (llr+llh)
    gated2_dual_k<<<gg, bg>>>(ll, gw_llr, gw_llh, llrg, llhg);
    cudaEventRecord(eDual, 0);

    // s2: pw2 after gated trio (needs llhg + masks)
    cudaStreamWaitEvent(s2, eDual, 0);
    conv1x1_mma<2><<<dim3(Nh2/128, 1, Bq), 256, CONV_SMEM, s2>>>(
        llhg, w_pw2, b_pw2, qcat + (size_t)Cc*Nh2, masks + (size_t)4*Cc*Nh2, Cc, Nh2,
        halfBS, catBS, 0, mBS);
    cudaEventRecord(ePw2, s2);

    // 0: pw1 (needs llrg + masks)
    cudaStreamWaitEvent(0, eM, 0);
    conv1x1_mma<2><<<dim3(Nh2/128, 1, Bq), 256, CONV_SMEM>>>(
        llrg, w_pw1, b_pw1, qcat, masks, Cc, Nh2, halfBS, catBS, 0, mBS);

    // 0: q_ll = conv1x1(cat, w_cat) + b_cat -> ll buffer
    cudaStreamWaitEvent(0, ePw2, 0);
    conv1x1_mma<0><<<dim3(Nh2/128, 1, Bq), 256, CONV_SMEM>>>(
        qcat, w_cat, b_cat, ll, nullptr, 2*Cc, Nh2, catBS, halfBS, 0, 0);

    // joins before fused gram
    cudaStreamWaitEvent(0, eG, 0);
    cudaStreamWaitEvent(0, eKV, 0);

    // 0: fused IDWT+gram, softmax-fold, final conv
    gram2_k<<<dim3(256/G2_T, NHh, Bq), 256>>>(ll, lhg, hlg, hhg, qkvd, gram);
    attw_k<<<Bq, 256>>>(gram, temper, w_out, weff);
    conv1x1_mma<0><<<dim3(Nf/128, 1, Bq), 256, CONV_SMEM>>>(
        qkvd + (size_t)2*Cc*Nf, weff, b_out, (float*)d_out, nullptr, Cc, Nf,
        qkvBS, fullBS, (size_t)Cc*Cc, 0);
}

// round 15
// speedup vs baseline: 1.0324x; 1.0324x over previous
#include <cuda_runtime.h>
#include <cuda_bf16.h>
#include <cstdint>
#include <math.h>

// ---------------- problem constants ----------------
#define Bq   2
#define Cc   128
#define Hf   256
#define Wf   256
#define Nf   (Hf*Wf)      // 65536
#define Hh   128
#define Wh   128
#define Nh2  (Hh*Wh)      // 16384
#define NHh  8
#define HD   16

#define HB   ((size_t)Bq*Cc*Nh2)

// ---------------- device scratch ----------------
__device__ float g_qkv [(size_t)Bq*3*Cc*Nf];
__device__ float g_qkvd[(size_t)Bq*3*Cc*Nf];
__device__ float g_hbuf[10*((size_t)Bq*Cc*Nh2)];
__device__ float g_masks[(size_t)Bq*5*Cc*Nh2];
__device__ float g_qcat [(size_t)Bq*2*Cc*Nh2];
__device__ float g_gram [Bq*NHh*288];
__device__ float g_weff [Bq*Cc*Cc];

__device__ __forceinline__ float sigm(float v) { return 1.f/(1.f+__expf(-v)); }

// =====================================================================
// tf32 helpers
// =====================================================================
__device__ __forceinline__ uint32_t f2tf32(float f) {
    uint32_t r;
    asm("cvt.rna.tf32.f32 %0, %1;" : "=r"(r) : "f"(f));
    return r;
}
__device__ __forceinline__ void mma_tf32(float c[4], const uint32_t a[4], const uint32_t b[2]) {
    asm volatile(
        "mma.sync.aligned.m16n8k8.row.col.f32.tf32.tf32.f32 "
        "{%0,%1,%2,%3}, {%4,%5,%6,%7}, {%8,%9}, {%0,%1,%2,%3};"
        : "+f"(c[0]), "+f"(c[1]), "+f"(c[2]), "+f"(c[3])
        : "r"(a[0]), "r"(a[1]), "r"(a[2]), "r"(a[3]), "r"(b[0]), "r"(b[1]));
}

// =====================================================================
// conv1x1 tf32 GEMM — double-buffered A&B, one sync per 32-K stage (R11)
// =====================================================================
#define A_STR 36
#define B_STR 132
#define AWRD (128*A_STR)
#define BWRD (32*B_STR)
#define CONV_SMEM ((2*AWRD + 2*BWRD)*4)   // 70656 bytes

template<int EPI>
__global__ void __launch_bounds__(256, 2) conv1x1_mma(
    const float* __restrict__ in, const float* __restrict__ w,
    const float* __restrict__ bias, float* __restrict__ out,
    const float* __restrict__ mask,
    int Cin, int P,
    size_t inBS, size_t outBS, size_t wBS, size_t maskBS)
{
    extern __shared__ uint32_t sdyn[];
    uint32_t* const Asb[2] = { sdyn, sdyn + AWRD };
    uint32_t* const Bsb[2] = { sdyn + 2*AWRD, sdyn + 2*AWRD + BWRD };

    const int b = blockIdx.z;
    in  += (size_t)b * inBS;
    out += (size_t)b * outBS;
    w   += (size_t)b * wBS;
    if (EPI == 2) mask += (size_t)b * maskBS;

    const int p0 = blockIdx.x * 128;
    const int o0 = blockIdx.y * 128;

    const int t = threadIdx.x;
    const int lane = t & 31;
    const int wrp  = t >> 5;
    const int wm   = wrp & 3;
    const int wn   = wrp >> 2;
    const int gid  = lane >> 2;
    const int tig  = lane & 3;

    int aOff[4], bOff[4];
#pragma unroll
    for (int i = 0; i < 4; i++) {
        const int slot = t + i * 256;
        aOff[i] = (slot >> 3) * A_STR + (slot & 7) * 4;
        bOff[i] = (slot >> 5) * B_STR + (slot & 31) * 4;
    }

    float acc[2][8][4];
#pragma unroll
    for (int i = 0; i < 2; i++)
#pragma unroll
        for (int j = 0; j < 8; j++)
#pragma unroll
            for (int r = 0; r < 4; r++) acc[i][j][r] = 0.f;

    const int nStages = Cin >> 5;

    float4 aPre[4], bPre[4];
    auto loadStage = [&](int s) {
        const float* wb = w + (size_t)o0 * Cin + (s << 5);
        const float* ib = in + (size_t)(s << 5) * P + p0;
#pragma unroll
        for (int i = 0; i < 4; i++) {
            const int slot = t + i * 256;
            aPre[i] = *(const float4*)(wb + (size_t)(slot >> 3) * Cin + (slot & 7) * 4);
            bPre[i] = *(const float4*)(ib + (size_t)(slot >> 5) * P + (slot & 31) * 4);
        }
    };
    auto stsStage = [&](int buf) {
        uint32_t* As = Asb[buf];
        uint32_t* Bs = Bsb[buf];
#pragma unroll
        for (int i = 0; i < 4; i++) {
            uint4 ua, ub;
            ua.x = f2tf32(aPre[i].x); ua.y = f2tf32(aPre[i].y);
            ua.z = f2tf32(aPre[i].z); ua.w = f2tf32(aPre[i].w);
            ub.x = f2tf32(bPre[i].x); ub.y = f2tf32(bPre[i].y);
            ub.z = f2tf32(bPre[i].z); ub.w = f2tf32(bPre[i].w);
            *(uint4*)(As + aOff[i]) = ua;
            *(uint4*)(Bs + bOff[i]) = ub;
        }
    };

    loadStage(0);
    stsStage(0);

    for (int stage = 0; stage < nStages; stage++) {
        const int buf = stage & 1;
        if (stage + 1 < nStages) loadStage(stage + 1);
        __syncthreads();

        const uint32_t* As = Asb[buf];
        const uint32_t* Bs = Bsb[buf];
#pragma unroll
        for (int k0 = 0; k0 < 32; k0 += 8) {
            uint32_t af[2][4];
#pragma unroll
            for (int tm = 0; tm < 2; tm++) {
                const int rb = wm * 32 + tm * 16;
                af[tm][0] = As[(rb + gid    ) * A_STR + k0 + tig    ];
                af[tm][1] = As[(rb + gid + 8) * A_STR + k0 + tig    ];
                af[tm][2] = As[(rb + gid    ) * A_STR + k0 + tig + 4];
                af[tm][3] = As[(rb + gid + 8) * A_STR + k0 + tig + 4];
            }
#pragma unroll
            for (int tn = 0; tn < 8; tn++) {
                uint32_t bf[2];
                const int col = wn * 64 + tn * 8 + gid;
                bf[0] = Bs[(k0 + tig    ) * B_STR + col];
                bf[1] = Bs[(k0 + tig + 4) * B_STR + col];
#pragma unroll
                for (int tm = 0; tm < 2; tm++)
                    mma_tf32(acc[tm][tn], af[tm], bf);
            }
        }
        if (stage + 1 < nStages) stsStage((stage + 1) & 1);
    }

#pragma unroll
    for (int tm = 0; tm < 2; tm++) {
        const int oA = o0 + wm * 32 + tm * 16 + gid;
        const int oB = oA + 8;
        const float bvA = __ldg(bias + oA);
        const float bvB = __ldg(bias + oB);
#pragma unroll
        for (int tn = 0; tn < 8; tn++) {
            const int p = p0 + wn * 64 + tn * 8 + tig * 2;
            float v0 = acc[tm][tn][0] + bvA;
            float v1 = acc[tm][tn][1] + bvA;
            float v2 = acc[tm][tn][2] + bvB;
            float v3 = acc[tm][tn][3] + bvB;
            if (EPI == 1) {
                v0 = sigm(v0); v1 = sigm(v1); v2 = sigm(v2); v3 = sigm(v3);
            }
            if (EPI == 2) {
                const float2 iA = *(const float2*)(in + (size_t)oA * P + p);
                const float2 iB = *(const float2*)(in + (size_t)oB * P + p);
                const float2 mA = *(const float2*)(mask + (size_t)oA * P + p);
                const float2 mB = *(const float2*)(mask + (size_t)oB * P + p);
                v0 = iA.x + v0 * mA.x; v1 = iA.y + v1 * mA.y;
                v2 = iB.x + v2 * mB.x; v3 = iB.y + v3 * mB.y;
            }
            *(float2*)(out + (size_t)oA * P + p) = make_float2(v0, v1);
            *(float2*)(out + (size_t)oB * P + p) = make_float2(v2, v3);
        }
    }
}

// =====================================================================
// depthwise 3x3 on k,v channels — 2 rows x 4 cols per thread
// (row reuse in registers: 4 row-loads produce 8 outputs)
// =====================================================================
__global__ void __launch_bounds__(256) dwconv3_k(
    const float* __restrict__ in, const float* __restrict__ wk,
    const float* __restrict__ wv, float* __restrict__ out)
{
    const int zc2 = blockIdx.z;
    const int b   = zc2 / (2*Cc);
    const int ch2 = zc2 % (2*Cc);
    const int cm  = ch2 % Cc;
    const float* ws = (ch2 < Cc) ? wk : wv;
    float wgt[9];
#pragma unroll
    for (int i=0;i<9;i++) wgt[i] = __ldg(ws + cm*9 + i);

    const size_t off = ((size_t)b*3*Cc + Cc + ch2)*Nf;
    const float* ip = in  + off;
    float*       op = out + off;

    const int x0 = (blockIdx.x*32 + threadIdx.x)*4;
    const int y0 = (blockIdx.y*8  + threadIdx.y)*2;

    float r[4][6];
#pragma unroll
    for (int dy=0; dy<4; dy++) {
        const int yy = y0 + dy - 1;
        const bool rv = (unsigned)yy < (unsigned)Hf;
        const float* rp = ip + (size_t)yy*Wf;
        if (rv) {
            const float4 m = *(const float4*)(rp + x0);
            r[dy][1]=m.x; r[dy][2]=m.y; r[dy][3]=m.z; r[dy][4]=m.w;
            r[dy][0] = (x0 > 0)      ? __ldg(rp + x0 - 1) : 0.f;
            r[dy][5] = (x0 + 4 < Wf) ? __ldg(rp + x0 + 4) : 0.f;
        } else {
#pragma unroll
            for (int j=0;j<6;j++) r[dy][j] = 0.f;
        }
    }
    float o[2][4];
#pragma unroll
    for (int qy=0; qy<2; qy++)
#pragma unroll
        for (int j=0; j<4; j++) o[qy][j] = 0.f;
#pragma unroll
    for (int qy=0; qy<2; qy++)
#pragma unroll
        for (int dy=0; dy<3; dy++)
#pragma unroll
            for (int dx=0; dx<3; dx++) {
                const float wv_ = wgt[dy*3+dx];
#pragma unroll
                for (int j=0; j<4; j++)
                    o[qy][j] = fmaf(r[qy+dy][j+dx], wv_, o[qy][j]);
            }
    *(float4*)(op + (size_t)y0*Wf + x0)     = make_float4(o[0][0],o[0][1],o[0][2],o[0][3]);
    *(float4*)(op + (size_t)(y0+1)*Wf + x0) = make_float4(o[1][0],o[1][1],o[1][2],o[1][3]);
}

// =====================================================================
// fused dwconv3(q) + Haar DWT — 2 half-px/thread, float4 row loads
// =====================================================================
__global__ void __launch_bounds__(256) dwconv_dwt_k(
    const float* __restrict__ in, const float* __restrict__ wq,
    float* __restrict__ ll, float* __restrict__ lh,
    float* __restrict__ hl, float* __restrict__ hh)
{
    const int zc = blockIdx.z;               // b*C + ch
    const int b = zc / Cc, ch = zc % Cc;
    float wgt[9];
#pragma unroll
    for (int i=0;i<9;i++) wgt[i] = __ldg(wq + ch*9 + i);

    const float* ip = in + ((size_t)b*3*Cc + ch)*Nf;
    const size_t ho = (size_t)zc*Nh2;

    const int xq = blockIdx.x*32 + threadIdx.x;
    const int yh = blockIdx.y*8  + threadIdx.y;
    const int fx = xq*4;

    float r[4][6];
#pragma unroll
    for (int dy=0; dy<4; dy++) {
        const int yy = 2*yh + dy - 1;
        const bool rv = (unsigned)yy < (unsigned)Hf;
        const float* rp = ip + (size_t)yy*Wf;
        if (rv) {
            const float4 m = *(const float4*)(rp + fx);
            r[dy][1]=m.x; r[dy][2]=m.y; r[dy][3]=m.z; r[dy][4]=m.w;
            r[dy][0] = (fx > 0)      ? __ldg(rp + fx - 1) : 0.f;
            r[dy][5] = (fx + 4 < Wf) ? __ldg(rp + fx + 4) : 0.f;
        } else {
#pragma unroll
            for (int j=0;j<6;j++) r[dy][j] = 0.f;
        }
    }
    float o[2][4];
#pragma unroll
    for (int qy=0; qy<2; qy++)
#pragma unroll
        for (int k=0; k<4; k++) {
            float s = 0.f;
#pragma unroll
            for (int ky=0; ky<3; ky++)
#pragma unroll
                for (int kx=0; kx<3; kx++)
                    s = fmaf(r[qy+ky][k+kx], wgt[ky*3+kx], s);
            o[qy][k] = s;
        }
    const size_t p = ho + (size_t)yh*Wh + xq*2;
    float2 vll, vlh, vhl, vhh;
    {
        const float a=o[0][0], bb2=o[0][1], c=o[1][0], d=o[1][1];
        vll.x=(a+bb2+c+d)*0.5f; vlh.x=(a+bb2-c-d)*0.5f;
        vhl.x=(a-bb2+c-d)*0.5f; vhh.x=(a-bb2-c+d)*0.5f;
    }
    {
        const float a=o[0][2], bb2=o[0][3], c=o[1][2], d=o[1][3];
        vll.y=(a+bb2+c+d)*0.5f; vlh.y=(a+bb2-c-d)*0.5f;
        vhl.y=(a-bb2+c-d)*0.5f; vhh.y=(a-bb2-c+d)*0.5f;
    }
    *(float2*)(ll+p) = vll;
    *(float2*)(lh+p) = vlh;
    *(float2*)(hl+p) = vhl;
    *(float2*)(hh+p) = vhh;
}

// =====================================================================
// smem-tiled single-stage gated conv + mask premultiply
// =====================================================================
template<int KH,int KW>
__global__ void __launch_bounds__(256) gated_s(
    const float* __restrict__ in, const float* __restrict__ w,
    const float* __restrict__ masks, int bandOff,
    float* __restrict__ out)
{
    constexpr int HALO_Y = KH/2, HALO_X = KW/2;
    constexpr int TR = 8 + KH - 1;
    constexpr int TC = 128 + KW - 1;
    __shared__ float sm[TR][TC];
    __shared__ float wsm[2][KH*KW];

    const int zc = blockIdx.z;
    const int b  = zc / Cc;
    const int ch = zc % Cc;
    const int t  = threadIdx.y*32 + threadIdx.x;
    if (t < 2*KH*KW) {
        const int br = t / (KH*KW), i = t % (KH*KW);
        wsm[br][i] = __ldg(w + (size_t)br*Cc*KH*KW + (size_t)ch*KH*KW + i);
    }

    const float* ip = in + (size_t)zc*Nh2;
    const float* mp = masks + ((size_t)b*5*Cc + bandOff + ch)*Nh2;
    const int Y0 = blockIdx.y*8;

    for (int idx = t; idx < TR*TC; idx += 256) {
        const int r = idx / TC, c = idx % TC;
        const int gy = Y0 - HALO_Y + r, gx = c - HALO_X;
        sm[r][c] = ((unsigned)gy < (unsigned)Hh && (unsigned)gx < (unsigned)Wh)
                   ? __ldg(ip + (size_t)gy*Wh + gx) : 0.f;
    }
    __syncthreads();

    const int ty = threadIdx.y;
    const int x0 = threadIdx.x*4;
    float s0[4] = {0,0,0,0}, s1[4] = {0,0,0,0};
#pragma unroll
    for (int ky=0; ky<KH; ky++) {
        float row[KW+3];
#pragma unroll
        for (int j=0; j<KW+3; j++) row[j] = sm[ty+ky][x0+j];
#pragma unroll
        for (int kx=0; kx<KW; kx++) {
            const float a0 = wsm[0][ky*KW+kx], a1 = wsm[1][ky*KW+kx];
#pragma unroll
            for (int j=0; j<4; j++) {
                s0[j] = fmaf(row[j+kx], a0, s0[j]);
                s1[j] = fmaf(row[j+kx], a1, s1[j]);
            }
        }
    }
    const float4 mv = *(const float4*)(mp + (size_t)(Y0+ty)*Wh + x0);
    float4 o;
    o.x = s0[0]*sigm(s1[0])*mv.x; o.y = s0[1]*sigm(s1[1])*mv.y;
    o.z = s0[2]*sigm(s1[2])*mv.z; o.w = s0[3]*sigm(s1[3])*mv.w;
    *(float4*)(out + (size_t)zc*Nh2 + (size_t)(Y0+ty)*Wh + x0) = o;
}

// =====================================================================
// fused dual 2-stage gated chains, occupancy-capped regs
// =====================================================================
__global__ void __launch_bounds__(256, 5) gated2_dual_k(
    const float* __restrict__ in,
    const float* __restrict__ wA, const float* __restrict__ wB,
    float* __restrict__ outA, float* __restrict__ outB)
{
    __shared__ float sm[12][132];
    __shared__ float midA[10][132];
    __shared__ float midB[10][132];
    __shared__ float wsm[8][9];

    const int zc = blockIdx.z;
    const int ch = zc % Cc;
    const int t  = threadIdx.y*32 + threadIdx.x;

    if (t < 72) {
        const int set = t / 9, i = t % 9;
        const float* base = (set < 4) ? wA : wB;
        const int s4 = set & 3;
        wsm[set][i] = __ldg(base + (size_t)s4*Cc*9 + (size_t)ch*9 + i);
    }

    const float* ip = in + (size_t)zc*Nh2;
    const int Y0 = blockIdx.y*8;

    for (int idx = t; idx < 12*132; idx += 256) {
        const int r = idx / 132, c = idx % 132;
        const int gy = Y0 - 2 + r, gx = c - 2;
        sm[r][c] = ((unsigned)gy < (unsigned)Hh && (unsigned)gx < (unsigned)Wh)
                   ? __ldg(ip + (size_t)gy*Wh + gx) : 0.f;
    }
    __syncthreads();

    for (int idx = t; idx < 10*130; idx += 256) {
        const int r = idx / 130, c = idx % 130;
        const int gy = Y0 - 1 + r, gx = c - 1;
        float a0=0, a1=0, b0=0, b1=0;
        if ((unsigned)gy < (unsigned)Hh && (unsigned)gx < (unsigned)Wh) {
#pragma unroll
            for (int ky=0; ky<3; ky++)
#pragma unroll
                for (int kx=0; kx<3; kx++) {
                    const float v = sm[r+ky][c+kx];
                    const int i = ky*3+kx;
                    a0 = fmaf(v, wsm[0][i], a0);
                    a1 = fmaf(v, wsm[1][i], a1);
                    b0 = fmaf(v, wsm[4][i], b0);
                    b1 = fmaf(v, wsm[5][i], b1);
                }
        }
        midA[r][c] = a0 * sigm(a1);
        midB[r][c] = b0 * sigm(b1);
    }
    __syncthreads();

    const int ty = threadIdx.y;
    const int x0 = threadIdx.x*4;
    float sA0[4]={0,0,0,0}, sA1[4]={0,0,0,0}, sB0[4]={0,0,0,0}, sB1[4]={0,0,0,0};
#pragma unroll
    for (int ky=0; ky<3; ky++) {
        float rA[6], rB[6];
#pragma unroll
        for (int j=0; j<6; j++) { rA[j] = midA[ty+ky][x0+j]; rB[j] = midB[ty+ky][x0+j]; }
#pragma unroll
        for (int kx=0; kx<3; kx++) {
            const int i = ky*3+kx;
            const float a2_0 = wsm[2][i], a2_1 = wsm[3][i];
            const float b2_0 = wsm[6][i], b2_1 = wsm[7][i];
#pragma unroll
            for (int j=0; j<4; j++) {
                sA0[j] = fmaf(rA[j+kx], a2_0, sA0[j]);
                sA1[j] = fmaf(rA[j+kx], a2_1, sA1[j]);
                sB0[j] = fmaf(rB[j+kx], b2_0, sB0[j]);
                sB1[j] = fmaf(rB[j+kx], b2_1, sB1[j]);
            }
        }
    }
    const size_t op = (size_t)zc*Nh2 + (size_t)(Y0+ty)*Wh + x0;
    float4 oA, oB;
    oA.x = sA0[0]*sigm(sA1[0]); oA.y = sA0[1]*sigm(sA1[1]);
    oA.z = sA0[2]*sigm(sA1[2]); oA.w = sA0[3]*sigm(sA1[3]);
    oB.x = sB0[0]*sigm(sB1[0]); oB.y = sB0[1]*sigm(sB1[1]);
    oB.z = sB0[2]*sigm(sB1[2]); oB.w = sB0[3]*sigm(sB1[3]);
    *(float4*)(outA + op) = oA;
    *(float4*)(outB + op) = oB;
}

// =====================================================================
// fused IDWT + gram
// =====================================================================
#define G2_T 8
#define QS_STR 260
__global__ void __launch_bounds__(256) gram2_k(
    const float* __restrict__ ll, const float* __restrict__ lh,
    const float* __restrict__ hl, const float* __restrict__ hh,
    const float* __restrict__ kall, float* __restrict__ gram)
{
    const int h = blockIdx.y, b = blockIdx.z;
    const size_t cb = ((size_t)b*Cc + h*HD)*Nh2;
    const float* llb = ll + cb;
    const float* lhb = lh + cb;
    const float* hlb = hl + cb;
    const float* hhb = hh + cb;
    const float* kb  = kall + (size_t)b*3*Cc*Nf + (size_t)Cc*Nf + (size_t)h*HD*Nf;

    __shared__ float qs[16][QS_STR];
    __shared__ float ks[16][QS_STR];

    const int t = threadIdx.x;
    const int i = t >> 4, j = t & 15;
    float accS = 0.f, accQ = 0.f, accK = 0.f;

    for (int tt = 0; tt < G2_T; tt++) {
        const int tileId = blockIdx.x * G2_T + tt;
        const int yh  = tileId >> 1;
        const int xh0 = (tileId & 1) * 64;

#pragma unroll
        for (int e = 0; e < 4; e++) {
            const int idx = t + e*256;
            const int r = idx >> 6, xl = idx & 63;
            const size_t p = (size_t)r*Nh2 + (size_t)yh*Wh + xh0 + xl;
            const float vll = llb[p], vlh = lhb[p], vhl = hlb[p], vhh = hhb[p];
            const int xc = xl*2;
            qs[r][xc      ] = (vll+vlh+vhl+vhh)*0.5f;
            qs[r][xc+1    ] = (vll+vlh-vhl-vhh)*0.5f;
            qs[r][128+xc  ] = (vll-vlh+vhl-vhh)*0.5f;
            qs[r][128+xc+1] = (vll-vlh-vhl+vhh)*0.5f;
        }
        const size_t n0 = (size_t)(2*yh)*Wf + 2*xh0;
#pragma unroll
        for (int e = 0; e < 4; e++) {
            const int idx = t + e*256;
            const int r = idx >> 6, rem = idx & 63;
            const int row = rem >> 5, c4 = rem & 31;
            const float4 v = *(const float4*)(kb + (size_t)r*Nf + n0 + row*Wf + c4*4);
            *(float4*)&ks[r][row*128 + c4*4] = v;
        }
        __syncthreads();
#pragma unroll 8
        for (int nn = 0; nn < 256; nn++) {
            const float qv = qs[i][nn];
            const float kv = ks[j][nn];
            accS = fmaf(qv, kv, accS);
            if (j == 0) accQ = fmaf(qv, qv, accQ);
            if (i == 0) accK = fmaf(kv, kv, accK);
        }
        __syncthreads();
    }
    float* gp = gram + (size_t)(b*NHh + h)*288;
    atomicAdd(gp + i*16 + j, accS);
    if (j == 0) atomicAdd(gp + 256 + i, accQ);
    if (i == 0) atomicAdd(gp + 272 + j, accK);
}

// =====================================================================
// softmax + fold w_out
// =====================================================================
__global__ void attw_k(const float* __restrict__ gram,
                       const float* __restrict__ temp,
                       const float* __restrict__ wout,
                       float* __restrict__ weff)
{
    const int b = blockIdx.x;
    __shared__ float att[NHh][16][16];
    const int t = threadIdx.x;
    const float* gb = gram + (size_t)b*NHh*288;

    if (t < 128) {
        const int h = t >> 4, i = t & 15;
        const float* gp = gb + h*288;
        const float nq = fmaxf(sqrtf(gp[256+i]), 1e-12f);
        const float tv = temp[h];
        float logit[16];
        float mx = -1e30f;
#pragma unroll
        for (int j=0;j<16;j++) {
            const float nk = fmaxf(sqrtf(gp[272+j]), 1e-12f);
            const float l = gp[i*16+j] / (nq*nk) * tv;
            logit[j] = l;
            mx = fmaxf(mx, l);
        }
        float se = 0.f;
#pragma unroll
        for (int j=0;j<16;j++) { const float e = __expf(logit[j]-mx); logit[j]=e; se+=e; }
        const float inv = 1.f/se;
#pragma unroll
        for (int j=0;j<16;j++) att[h][i][j] = logit[j]*inv;
    }
    __syncthreads();

    float* wb = weff + (size_t)b*Cc*Cc;
    for (int idx = t; idx < Cc*Cc; idx += 256) {
        const int o = idx >> 7, cp = idx & 127;
        const int h = cp >> 4, j = cp & 15;
        float s = 0.f;
#pragma unroll
        for (int i=0;i<16;i++)
            s = fmaf(wout[(size_t)o*Cc + h*16 + i], att[h][i][j], s);
        wb[idx] = s;
    }
}

// =====================================================================
// host launch — exact R11 graph
// =====================================================================
extern "C" void kernel_launch(void* const* d_in, const int* in_sizes, int n_in,
                              void* d_out, int out_size)
{
    const float* x      = (const float*)d_in[0];
    const float* prior  = (const float*)d_in[1];
    const float* w_lin  = (const float*)d_in[2];
    const float* b_lin  = (const float*)d_in[3];
    const float* w_qd   = (const float*)d_in[4];
    const float* w_kd   = (const float*)d_in[5];
    const float* w_vd   = (const float*)d_in[6];
    const float* gw_llr = (const float*)d_in[7];
    const float* gw_llh = (const float*)d_in[8];
    const float* gw_lh  = (const float*)d_in[9];
    const float* gw_hl  = (const float*)d_in[10];
    const float* gw_hh  = (const float*)d_in[11];
    const float* w_prior= (const float*)d_in[12];
    const float* b_prior= (const float*)d_in[13];
    const float* w_pw1  = (const float*)d_in[14];
    const float* b_pw1  = (const float*)d_in[15];
    const float* w_pw2  = (const float*)d_in[16];
    const float* b_pw2  = (const float*)d_in[17];
    const float* w_cat  = (const float*)d_in[18];
    const float* b_cat  = (const float*)d_in[19];
    const float* temper = (const float*)d_in[20];
    const float* w_out  = (const float*)d_in[21];
    const float* b_out  = (const float*)d_in[22];

    float *qkv, *qkvd, *hbuf, *masks, *qcat, *gram, *weff;
    cudaGetSymbolAddress((void**)&qkv,   g_qkv);
    cudaGetSymbolAddress((void**)&qkvd,  g_qkvd);
    cudaGetSymbolAddress((void**)&hbuf,  g_hbuf);
    cudaGetSymbolAddress((void**)&masks, g_masks);
    cudaGetSymbolAddress((void**)&qcat,  g_qcat);
    cudaGetSymbolAddress((void**)&gram,  g_gram);
    cudaGetSymbolAddress((void**)&weff,  g_weff);

    static cudaStream_t s1 = nullptr, s2 = nullptr;
    static cudaEvent_t eStart = nullptr, eQkv = nullptr, eKV = nullptr,
                       eM = nullptr, eDWT = nullptr, eG = nullptr,
                       eDual = nullptr, ePw2 = nullptr;
    if (s1 == nullptr) {
        cudaStreamCreateWithFlags(&s1, cudaStreamNonBlocking);
        cudaStreamCreateWithFlags(&s2, cudaStreamNonBlocking);
        cudaEventCreateWithFlags(&eStart, cudaEventDisableTiming);
        cudaEventCreateWithFlags(&eQkv,   cudaEventDisableTiming);
        cudaEventCreateWithFlags(&eKV,    cudaEventDisableTiming);
        cudaEventCreateWithFlags(&eM,     cudaEventDisableTiming);
        cudaEventCreateWithFlags(&eDWT,   cudaEventDisableTiming);
        cudaEventCreateWithFlags(&eG,     cudaEventDisableTiming);
        cudaEventCreateWithFlags(&eDual,  cudaEventDisableTiming);
        cudaEventCreateWithFlags(&ePw2,   cudaEventDisableTiming);
        cudaFuncSetAttribute(conv1x1_mma<0>, cudaFuncAttributeMaxDynamicSharedMemorySize, CONV_SMEM);
        cudaFuncSetAttribute(conv1x1_mma<1>, cudaFuncAttributeMaxDynamicSharedMemorySize, CONV_SMEM);
        cudaFuncSetAttribute(conv1x1_mma<2>, cudaFuncAttributeMaxDynamicSharedMemorySize, CONV_SMEM);
    }

    float* ll   = hbuf + 0*HB;
    float* lh   = hbuf + 1*HB;
    float* hl   = hbuf + 2*HB;
    float* hh   = hbuf + 3*HB;
    float* llrg = hbuf + 5*HB;
    float* llhg = hbuf + 6*HB;
    float* lhg  = hbuf + 7*HB;
    float* hlg  = hbuf + 8*HB;
    float* hhg  = hbuf + 9*HB;

    const size_t fullBS = (size_t)Cc*Nf;
    const size_t qkvBS  = (size_t)3*Cc*Nf;
    const size_t halfBS = (size_t)Cc*Nh2;
    const size_t mBS    = (size_t)5*Cc*Nh2;
    const size_t catBS  = (size_t)2*Cc*Nh2;

    const size_t xel = (size_t)in_sizes[0];
    const size_t pel = (size_t)in_sizes[1];

    // fork side streams
    cudaEventRecord(eStart, 0);
    cudaStreamWaitEvent(s2, eStart, 0);
    cudaStreamWaitEvent(s1, eStart, 0);

    // s1: independent work first
    if ((size_t)out_size >= xel + pel) {
        cudaMemcpyAsync((float*)d_out + xel, prior, pel*sizeof(float),
                        cudaMemcpyDeviceToDevice, s1);
    }
    cudaMemsetAsync(gram, 0, (size_t)Bq*NHh*288*sizeof(float), s1);

    // s2: masks = sigmoid(conv1x1(prior))
    conv1x1_mma<1><<<dim3(Nh2/128, 5, Bq), 256, CONV_SMEM, s2>>>(
        prior, w_prior, b_prior, masks, nullptr, Cc, Nh2, halfBS, mBS, 0, 0);
    cudaEventRecord(eM, s2);

    // 0: qkv = conv1x1(x, w_lin) + b_lin
    conv1x1_mma<0><<<dim3(Nf/128, 3, Bq), 256, CONV_SMEM>>>(
        x, w_lin, b_lin, qkv, nullptr, Cc, Nf, fullBS, qkvBS, 0, 0);
    cudaEventRecord(eQkv, 0);

    // s1: depthwise 3x3 on k,v (2 rows/thread)
    cudaStreamWaitEvent(s1, eQkv, 0);
    dwconv3_k<<<dim3(Wf/128, Hf/16, Bq*2*Cc), dim3(32,8), 0, s1>>>(qkv, w_kd, w_vd, qkvd);
    cudaEventRecord(eKV, s1);

    // 0: fused dwconv(q)+DWT
    dwconv_dwt_k<<<dim3(2, Hh/8, Bq*Cc), dim3(32,8)>>>(qkv, w_qd, ll, lh, hl, hh);
    cudaEventRecord(eDWT, 0);

    dim3 gg(1, Hh/8, Bq*Cc), bg(32,8);

    // s2: single-stage gated convs with mask premultiply (masks already on s2)
    cudaStreamWaitEvent(s2, eDWT, 0);
    gated_s<3,5><<<gg, bg, 0, s2>>>(lh, gw_lh, masks, 1*Cc, lhg);
    gated_s<5,3><<<gg, bg, 0, s2>>>(hl, gw_hl, masks, 2*Cc, hlg);
    gated_s<3,3><<<gg, bg, 0, s2>>>(hh, gw_hh, masks, 3*Cc, hhg);
    cudaEventRecord(eG, s2);

    // 0: dual gated chain (llr+llh)
    gated2_dual_k<<<gg, bg>>>(ll, gw_llr, gw_llh, llrg, llhg);
    cudaEventRecord(eDual, 0);

    // s1: pw2 — concurrent with pw1 on 0
    cudaStreamWaitEvent(s1, eDual, 0);
    cudaStreamWaitEvent(s1, eM, 0);
    conv1x1_mma<2><<<dim3(Nh2/128, 1, Bq), 256, CONV_SMEM, s1>>>(
        llhg, w_pw2, b_pw2, qcat + (size_t)Cc*Nh2, masks + (size_t)4*Cc*Nh2, Cc, Nh2,
        halfBS, catBS, 0, mBS);
    cudaEventRecord(ePw2, s1);

    // 0: pw1
    cudaStreamWaitEvent(0, eM, 0);
    conv1x1_mma<2><<<dim3(Nh2/128, 1, Bq), 256, CONV_SMEM>>>(
        llrg, w_pw1, b_pw1, qcat, masks, Cc, Nh2, halfBS, catBS, 0, mBS);

    // 0: q_ll = conv1x1(cat, w_cat) + b_cat -> ll buffer
    cudaStreamWaitEvent(0, ePw2, 0);
    conv1x1_mma<0><<<dim3(Nh2/128, 1, Bq), 256, CONV_SMEM>>>(
        qcat, w_cat, b_cat, ll, nullptr, 2*Cc, Nh2, catBS, halfBS, 0, 0);

    // joins before fused gram
    cudaStreamWaitEvent(0, eG, 0);
    cudaStreamWaitEvent(0, eKV, 0);

    // 0: fused IDWT+gram, softmax-fold, final conv
    gram2_k<<<dim3(256/G2_T, NHh, Bq), 256>>>(ll, lhg, hlg, hhg, qkvd, gram);
    attw_k<<<Bq, 256>>>(gram, temper, w_out, weff);
    conv1x1_mma<0><<<dim3(Nf/128, 1, Bq), 256, CONV_SMEM>>>(
        qkvd + (size_t)2*Cc*Nf, weff, b_out, (float*)d_out, nullptr, Cc, Nf,
        qkvBS, fullBS, (size_t)Cc*Cc, 0);
}

// round 16
// speedup vs baseline: 1.0393x; 1.0067x over previous
#include <cuda_runtime.h>
#include <cuda_bf16.h>
#include <cstdint>
#include <math.h>

// ---------------- problem constants ----------------
#define Bq   2
#define Cc   128
#define Hf   256
#define Wf   256
#define Nf   (Hf*Wf)      // 65536
#define Hh   128
#define Wh   128
#define Nh2  (Hh*Wh)      // 16384
#define NHh  8
#define HD   16

#define HB   ((size_t)Bq*Cc*Nh2)

// ---------------- device scratch ----------------
__device__ float g_qkv [(size_t)Bq*3*Cc*Nf];
__device__ float g_qkvd[(size_t)Bq*3*Cc*Nf];
__device__ float g_hbuf[10*((size_t)Bq*Cc*Nh2)];
__device__ float g_masks[(size_t)Bq*5*Cc*Nh2];
__device__ float g_qcat [(size_t)Bq*2*Cc*Nh2];
__device__ float g_gram [Bq*NHh*288];
__device__ float g_weff [Bq*Cc*Cc];

__device__ __forceinline__ float sigm(float v) { return 1.f/(1.f+__expf(-v)); }

// =====================================================================
// tf32 helpers
// =====================================================================
__device__ __forceinline__ uint32_t f2tf32(float f) {
    uint32_t r;
    asm("cvt.rna.tf32.f32 %0, %1;" : "=r"(r) : "f"(f));
    return r;
}
__device__ __forceinline__ void mma_tf32(float c[4], const uint32_t a[4], const uint32_t b[2]) {
    asm volatile(
        "mma.sync.aligned.m16n8k8.row.col.f32.tf32.tf32.f32 "
        "{%0,%1,%2,%3}, {%4,%5,%6,%7}, {%8,%9}, {%0,%1,%2,%3};"
        : "+f"(c[0]), "+f"(c[1]), "+f"(c[2]), "+f"(c[3])
        : "r"(a[0]), "r"(a[1]), "r"(a[2]), "r"(a[3]), "r"(b[0]), "r"(b[1]));
}

// =====================================================================
// conv1x1 tf32 GEMM — double-buffered A&B, one sync per 32-K stage (R11)
// =====================================================================
#define A_STR 36
#define B_STR 132
#define AWRD (128*A_STR)
#define BWRD (32*B_STR)
#define CONV_SMEM ((2*AWRD + 2*BWRD)*4)   // 70656 bytes

template<int EPI>
__global__ void __launch_bounds__(256, 2) conv1x1_mma(
    const float* __restrict__ in, const float* __restrict__ w,
    const float* __restrict__ bias, float* __restrict__ out,
    const float* __restrict__ mask,
    int Cin, int P,
    size_t inBS, size_t outBS, size_t wBS, size_t maskBS)
{
    extern __shared__ uint32_t sdyn[];
    uint32_t* const Asb[2] = { sdyn, sdyn + AWRD };
    uint32_t* const Bsb[2] = { sdyn + 2*AWRD, sdyn + 2*AWRD + BWRD };

    const int b = blockIdx.z;
    in  += (size_t)b * inBS;
    out += (size_t)b * outBS;
    w   += (size_t)b * wBS;
    if (EPI == 2) mask += (size_t)b * maskBS;

    const int p0 = blockIdx.x * 128;
    const int o0 = blockIdx.y * 128;

    const int t = threadIdx.x;
    const int lane = t & 31;
    const int wrp  = t >> 5;
    const int wm   = wrp & 3;
    const int wn   = wrp >> 2;
    const int gid  = lane >> 2;
    const int tig  = lane & 3;

    int aOff[4], bOff[4];
#pragma unroll
    for (int i = 0; i < 4; i++) {
        const int slot = t + i * 256;
        aOff[i] = (slot >> 3) * A_STR + (slot & 7) * 4;
        bOff[i] = (slot >> 5) * B_STR + (slot & 31) * 4;
    }

    float acc[2][8][4];
#pragma unroll
    for (int i = 0; i < 2; i++)
#pragma unroll
        for (int j = 0; j < 8; j++)
#pragma unroll
            for (int r = 0; r < 4; r++) acc[i][j][r] = 0.f;

    const int nStages = Cin >> 5;

    float4 aPre[4], bPre[4];
    auto loadStage = [&](int s) {
        const float* wb = w + (size_t)o0 * Cin + (s << 5);
        const float* ib = in + (size_t)(s << 5) * P + p0;
#pragma unroll
        for (int i = 0; i < 4; i++) {
            const int slot = t + i * 256;
            aPre[i] = *(const float4*)(wb + (size_t)(slot >> 3) * Cin + (slot & 7) * 4);
            bPre[i] = *(const float4*)(ib + (size_t)(slot >> 5) * P + (slot & 31) * 4);
        }
    };
    auto stsStage = [&](int buf) {
        uint32_t* As = Asb[buf];
        uint32_t* Bs = Bsb[buf];
#pragma unroll
        for (int i = 0; i < 4; i++) {
            uint4 ua, ub;
            ua.x = f2tf32(aPre[i].x); ua.y = f2tf32(aPre[i].y);
            ua.z = f2tf32(aPre[i].z); ua.w = f2tf32(aPre[i].w);
            ub.x = f2tf32(bPre[i].x); ub.y = f2tf32(bPre[i].y);
            ub.z = f2tf32(bPre[i].z); ub.w = f2tf32(bPre[i].w);
            *(uint4*)(As + aOff[i]) = ua;
            *(uint4*)(Bs + bOff[i]) = ub;
        }
    };

    loadStage(0);
    stsStage(0);

    for (int stage = 0; stage < nStages; stage++) {
        const int buf = stage & 1;
        if (stage + 1 < nStages) loadStage(stage + 1);
        __syncthreads();

        const uint32_t* As = Asb[buf];
        const uint32_t* Bs = Bsb[buf];
#pragma unroll
        for (int k0 = 0; k0 < 32; k0 += 8) {
            uint32_t af[2][4];
#pragma unroll
            for (int tm = 0; tm < 2; tm++) {
                const int rb = wm * 32 + tm * 16;
                af[tm][0] = As[(rb + gid    ) * A_STR + k0 + tig    ];
                af[tm][1] = As[(rb + gid + 8) * A_STR + k0 + tig    ];
                af[tm][2] = As[(rb + gid    ) * A_STR + k0 + tig + 4];
                af[tm][3] = As[(rb + gid + 8) * A_STR + k0 + tig + 4];
            }
#pragma unroll
            for (int tn = 0; tn < 8; tn++) {
                uint32_t bf[2];
                const int col = wn * 64 + tn * 8 + gid;
                bf[0] = Bs[(k0 + tig    ) * B_STR + col];
                bf[1] = Bs[(k0 + tig + 4) * B_STR + col];
#pragma unroll
                for (int tm = 0; tm < 2; tm++)
                    mma_tf32(acc[tm][tn], af[tm], bf);
            }
        }
        if (stage + 1 < nStages) stsStage((stage + 1) & 1);
    }

#pragma unroll
    for (int tm = 0; tm < 2; tm++) {
        const int oA = o0 + wm * 32 + tm * 16 + gid;
        const int oB = oA + 8;
        const float bvA = __ldg(bias + oA);
        const float bvB = __ldg(bias + oB);
#pragma unroll
        for (int tn = 0; tn < 8; tn++) {
            const int p = p0 + wn * 64 + tn * 8 + tig * 2;
            float v0 = acc[tm][tn][0] + bvA;
            float v1 = acc[tm][tn][1] + bvA;
            float v2 = acc[tm][tn][2] + bvB;
            float v3 = acc[tm][tn][3] + bvB;
            if (EPI == 1) {
                v0 = sigm(v0); v1 = sigm(v1); v2 = sigm(v2); v3 = sigm(v3);
            }
            if (EPI == 2) {
                const float2 iA = *(const float2*)(in + (size_t)oA * P + p);
                const float2 iB = *(const float2*)(in + (size_t)oB * P + p);
                const float2 mA = *(const float2*)(mask + (size_t)oA * P + p);
                const float2 mB = *(const float2*)(mask + (size_t)oB * P + p);
                v0 = iA.x + v0 * mA.x; v1 = iA.y + v1 * mA.y;
                v2 = iB.x + v2 * mB.x; v3 = iB.y + v3 * mB.y;
            }
            *(float2*)(out + (size_t)oA * P + p) = make_float2(v0, v1);
            *(float2*)(out + (size_t)oB * P + p) = make_float2(v2, v3);
        }
    }
}

// =====================================================================
// depthwise 3x3 on k,v channels — 2 rows x 4 cols per thread (R15)
// =====================================================================
__global__ void __launch_bounds__(256) dwconv3_k(
    const float* __restrict__ in, const float* __restrict__ wk,
    const float* __restrict__ wv, float* __restrict__ out)
{
    const int zc2 = blockIdx.z;
    const int b   = zc2 / (2*Cc);
    const int ch2 = zc2 % (2*Cc);
    const int cm  = ch2 % Cc;
    const float* ws = (ch2 < Cc) ? wk : wv;
    float wgt[9];
#pragma unroll
    for (int i=0;i<9;i++) wgt[i] = __ldg(ws + cm*9 + i);

    const size_t off = ((size_t)b*3*Cc + Cc + ch2)*Nf;
    const float* ip = in  + off;
    float*       op = out + off;

    const int x0 = (blockIdx.x*32 + threadIdx.x)*4;
    const int y0 = (blockIdx.y*8  + threadIdx.y)*2;

    float r[4][6];
#pragma unroll
    for (int dy=0; dy<4; dy++) {
        const int yy = y0 + dy - 1;
        const bool rv = (unsigned)yy < (unsigned)Hf;
        const float* rp = ip + (size_t)yy*Wf;
        if (rv) {
            const float4 m = *(const float4*)(rp + x0);
            r[dy][1]=m.x; r[dy][2]=m.y; r[dy][3]=m.z; r[dy][4]=m.w;
            r[dy][0] = (x0 > 0)      ? __ldg(rp + x0 - 1) : 0.f;
            r[dy][5] = (x0 + 4 < Wf) ? __ldg(rp + x0 + 4) : 0.f;
        } else {
#pragma unroll
            for (int j=0;j<6;j++) r[dy][j] = 0.f;
        }
    }
    float o[2][4];
#pragma unroll
    for (int qy=0; qy<2; qy++)
#pragma unroll
        for (int j=0; j<4; j++) o[qy][j] = 0.f;
#pragma unroll
    for (int qy=0; qy<2; qy++)
#pragma unroll
        for (int dy=0; dy<3; dy++)
#pragma unroll
            for (int dx=0; dx<3; dx++) {
                const float wv_ = wgt[dy*3+dx];
#pragma unroll
                for (int j=0; j<4; j++)
                    o[qy][j] = fmaf(r[qy+dy][j+dx], wv_, o[qy][j]);
            }
    *(float4*)(op + (size_t)y0*Wf + x0)     = make_float4(o[0][0],o[0][1],o[0][2],o[0][3]);
    *(float4*)(op + (size_t)(y0+1)*Wf + x0) = make_float4(o[1][0],o[1][1],o[1][2],o[1][3]);
}

// =====================================================================
// fused dwconv3(q) + Haar DWT — 2 half-rows x 2 half-px per thread
// (6 full-res row-loads -> 4 conv rows -> 8 half-res outputs)
// =====================================================================
__global__ void __launch_bounds__(256) dwconv_dwt_k(
    const float* __restrict__ in, const float* __restrict__ wq,
    float* __restrict__ ll, float* __restrict__ lh,
    float* __restrict__ hl, float* __restrict__ hh)
{
    const int zc = blockIdx.z;               // b*C + ch
    const int b = zc / Cc, ch = zc % Cc;
    float wgt[9];
#pragma unroll
    for (int i=0;i<9;i++) wgt[i] = __ldg(wq + ch*9 + i);

    const float* ip = in + ((size_t)b*3*Cc + ch)*Nf;
    const size_t ho = (size_t)zc*Nh2;

    const int xq  = blockIdx.x*32 + threadIdx.x;      // half-res pair idx 0..63
    const int yh0 = (blockIdx.y*8 + threadIdx.y)*2;   // 2 half-rows per thread
    const int fx  = xq*4;

    float r[6][6];
#pragma unroll
    for (int dy=0; dy<6; dy++) {
        const int yy = 2*yh0 + dy - 1;
        const bool rv = (unsigned)yy < (unsigned)Hf;
        const float* rp = ip + (size_t)yy*Wf;
        if (rv) {
            const float4 m = *(const float4*)(rp + fx);
            r[dy][1]=m.x; r[dy][2]=m.y; r[dy][3]=m.z; r[dy][4]=m.w;
            r[dy][0] = (fx > 0)      ? __ldg(rp + fx - 1) : 0.f;
            r[dy][5] = (fx + 4 < Wf) ? __ldg(rp + fx + 4) : 0.f;
        } else {
#pragma unroll
            for (int j=0;j<6;j++) r[dy][j] = 0.f;
        }
    }
    float o[4][4];
#pragma unroll
    for (int qy=0; qy<4; qy++)
#pragma unroll
        for (int k=0; k<4; k++) {
            float s = 0.f;
#pragma unroll
            for (int ky=0; ky<3; ky++)
#pragma unroll
                for (int kx=0; kx<3; kx++)
                    s = fmaf(r[qy+ky][k+kx], wgt[ky*3+kx], s);
            o[qy][k] = s;
        }
#pragma unroll
    for (int hr=0; hr<2; hr++) {
        const size_t p = ho + (size_t)(yh0+hr)*Wh + xq*2;
        float2 vll, vlh, vhl, vhh;
        {
            const float a=o[2*hr][0], bb2=o[2*hr][1], c=o[2*hr+1][0], d=o[2*hr+1][1];
            vll.x=(a+bb2+c+d)*0.5f; vlh.x=(a+bb2-c-d)*0.5f;
            vhl.x=(a-bb2+c-d)*0.5f; vhh.x=(a-bb2-c+d)*0.5f;
        }
        {
            const float a=o[2*hr][2], bb2=o[2*hr][3], c=o[2*hr+1][2], d=o[2*hr+1][3];
            vll.y=(a+bb2+c+d)*0.5f; vlh.y=(a+bb2-c-d)*0.5f;
            vhl.y=(a-bb2+c-d)*0.5f; vhh.y=(a-bb2-c+d)*0.5f;
        }
        *(float2*)(ll+p) = vll;
        *(float2*)(lh+p) = vlh;
        *(float2*)(hl+p) = vhl;
        *(float2*)(hh+p) = vhh;
    }
}

// =====================================================================
// smem-tiled single-stage gated conv + mask premultiply
// =====================================================================
template<int KH,int KW>
__global__ void __launch_bounds__(256) gated_s(
    const float* __restrict__ in, const float* __restrict__ w,
    const float* __restrict__ masks, int bandOff,
    float* __restrict__ out)
{
    constexpr int HALO_Y = KH/2, HALO_X = KW/2;
    constexpr int TR = 8 + KH - 1;
    constexpr int TC = 128 + KW - 1;
    __shared__ float sm[TR][TC];
    __shared__ float wsm[2][KH*KW];

    const int zc = blockIdx.z;
    const int b  = zc / Cc;
    const int ch = zc % Cc;
    const int t  = threadIdx.y*32 + threadIdx.x;
    if (t < 2*KH*KW) {
        const int br = t / (KH*KW), i = t % (KH*KW);
        wsm[br][i] = __ldg(w + (size_t)br*Cc*KH*KW + (size_t)ch*KH*KW + i);
    }

    const float* ip = in + (size_t)zc*Nh2;
    const float* mp = masks + ((size_t)b*5*Cc + bandOff + ch)*Nh2;
    const int Y0 = blockIdx.y*8;

    for (int idx = t; idx < TR*TC; idx += 256) {
        const int r = idx / TC, c = idx % TC;
        const int gy = Y0 - HALO_Y + r, gx = c - HALO_X;
        sm[r][c] = ((unsigned)gy < (unsigned)Hh && (unsigned)gx < (unsigned)Wh)
                   ? __ldg(ip + (size_t)gy*Wh + gx) : 0.f;
    }
    __syncthreads();

    const int ty = threadIdx.y;
    const int x0 = threadIdx.x*4;
    float s0[4] = {0,0,0,0}, s1[4] = {0,0,0,0};
#pragma unroll
    for (int ky=0; ky<KH; ky++) {
        float row[KW+3];
#pragma unroll
        for (int j=0; j<KW+3; j++) row[j] = sm[ty+ky][x0+j];
#pragma unroll
        for (int kx=0; kx<KW; kx++) {
            const float a0 = wsm[0][ky*KW+kx], a1 = wsm[1][ky*KW+kx];
#pragma unroll
            for (int j=0; j<4; j++) {
                s0[j] = fmaf(row[j+kx], a0, s0[j]);
                s1[j] = fmaf(row[j+kx], a1, s1[j]);
            }
        }
    }
    const float4 mv = *(const float4*)(mp + (size_t)(Y0+ty)*Wh + x0);
    float4 o;
    o.x = s0[0]*sigm(s1[0])*mv.x; o.y = s0[1]*sigm(s1[1])*mv.y;
    o.z = s0[2]*sigm(s1[2])*mv.z; o.w = s0[3]*sigm(s1[3])*mv.w;
    *(float4*)(out + (size_t)zc*Nh2 + (size_t)(Y0+ty)*Wh + x0) = o;
}

// =====================================================================
// fused dual 2-stage gated chains, occupancy-capped regs
// =====================================================================
__global__ void __launch_bounds__(256, 5) gated2_dual_k(
    const float* __restrict__ in,
    const float* __restrict__ wA, const float* __restrict__ wB,
    float* __restrict__ outA, float* __restrict__ outB)
{
    __shared__ float sm[12][132];
    __shared__ float midA[10][132];
    __shared__ float midB[10][132];
    __shared__ float wsm[8][9];

    const int zc = blockIdx.z;
    const int ch = zc % Cc;
    const int t  = threadIdx.y*32 + threadIdx.x;

    if (t < 72) {
        const int set = t / 9, i = t % 9;
        const float* base = (set < 4) ? wA : wB;
        const int s4 = set & 3;
        wsm[set][i] = __ldg(base + (size_t)s4*Cc*9 + (size_t)ch*9 + i);
    }

    const float* ip = in + (size_t)zc*Nh2;
    const int Y0 = blockIdx.y*8;

    for (int idx = t; idx < 12*132; idx += 256) {
        const int r = idx / 132, c = idx % 132;
        const int gy = Y0 - 2 + r, gx = c - 2;
        sm[r][c] = ((unsigned)gy < (unsigned)Hh && (unsigned)gx < (unsigned)Wh)
                   ? __ldg(ip + (size_t)gy*Wh + gx) : 0.f;
    }
    __syncthreads();

    for (int idx = t; idx < 10*130; idx += 256) {
        const int r = idx / 130, c = idx % 130;
        const int gy = Y0 - 1 + r, gx = c - 1;
        float a0=0, a1=0, b0=0, b1=0;
        if ((unsigned)gy < (unsigned)Hh && (unsigned)gx < (unsigned)Wh) {
#pragma unroll
            for (int ky=0; ky<3; ky++)
#pragma unroll
                for (int kx=0; kx<3; kx++) {
                    const float v = sm[r+ky][c+kx];
                    const int i = ky*3+kx;
                    a0 = fmaf(v, wsm[0][i], a0);
                    a1 = fmaf(v, wsm[1][i], a1);
                    b0 = fmaf(v, wsm[4][i], b0);
                    b1 = fmaf(v, wsm[5][i], b1);
                }
        }
        midA[r][c] = a0 * sigm(a1);
        midB[r][c] = b0 * sigm(b1);
    }
    __syncthreads();

    const int ty = threadIdx.y;
    const int x0 = threadIdx.x*4;
    float sA0[4]={0,0,0,0}, sA1[4]={0,0,0,0}, sB0[4]={0,0,0,0}, sB1[4]={0,0,0,0};
#pragma unroll
    for (int ky=0; ky<3; ky++) {
        float rA[6], rB[6];
#pragma unroll
        for (int j=0; j<6; j++) { rA[j] = midA[ty+ky][x0+j]; rB[j] = midB[ty+ky][x0+j]; }
#pragma unroll
        for (int kx=0; kx<3; kx++) {
            const int i = ky*3+kx;
            const float a2_0 = wsm[2][i], a2_1 = wsm[3][i];
            const float b2_0 = wsm[6][i], b2_1 = wsm[7][i];
#pragma unroll
            for (int j=0; j<4; j++) {
                sA0[j] = fmaf(rA[j+kx], a2_0, sA0[j]);
                sA1[j] = fmaf(rA[j+kx], a2_1, sA1[j]);
                sB0[j] = fmaf(rB[j+kx], b2_0, sB0[j]);
                sB1[j] = fmaf(rB[j+kx], b2_1, sB1[j]);
            }
        }
    }
    const size_t op = (size_t)zc*Nh2 + (size_t)(Y0+ty)*Wh + x0;
    float4 oA, oB;
    oA.x = sA0[0]*sigm(sA1[0]); oA.y = sA0[1]*sigm(sA1[1]);
    oA.z = sA0[2]*sigm(sA1[2]); oA.w = sA0[3]*sigm(sA1[3]);
    oB.x = sB0[0]*sigm(sB1[0]); oB.y = sB0[1]*sigm(sB1[1]);
    oB.z = sB0[2]*sigm(sB1[2]); oB.w = sB0[3]*sigm(sB1[3]);
    *(float4*)(outA + op) = oA;
    *(float4*)(outB + op) = oB;
}

// =====================================================================
// fused IDWT + gram — float2 band loads, float4 qs stores
// =====================================================================
#define G2_T 8
#define QS_STR 260
__global__ void __launch_bounds__(256) gram2_k(
    const float* __restrict__ ll, const float* __restrict__ lh,
    const float* __restrict__ hl, const float* __restrict__ hh,
    const float* __restrict__ kall, float* __restrict__ gram)
{
    const int h = blockIdx.y, b = blockIdx.z;
    const size_t cb = ((size_t)b*Cc + h*HD)*Nh2;
    const float* llb = ll + cb;
    const float* lhb = lh + cb;
    const float* hlb = hl + cb;
    const float* hhb = hh + cb;
    const float* kb  = kall + (size_t)b*3*Cc*Nf + (size_t)Cc*Nf + (size_t)h*HD*Nf;

    __shared__ float qs[16][QS_STR];
    __shared__ float ks[16][QS_STR];

    const int t = threadIdx.x;
    const int i = t >> 4, j = t & 15;
    float accS = 0.f, accQ = 0.f, accK = 0.f;

    for (int tt = 0; tt < G2_T; tt++) {
        const int tileId = blockIdx.x * G2_T + tt;
        const int yh  = tileId >> 1;
        const int xh0 = (tileId & 1) * 64;

        // stage q: each thread loads a half-res xl PAIR from all 4 bands,
        // writes two IDWT quads as float4 (rows 0 and 1 of the tile).
#pragma unroll
        for (int e = 0; e < 2; e++) {
            const int idx = t + e*256;           // 512 pair-slots
            const int r = idx >> 5, xp = idx & 31;
            const size_t p = (size_t)r*Nh2 + (size_t)yh*Wh + xh0 + xp*2;
            const float2 l2 = *(const float2*)(llb+p);
            const float2 a2 = *(const float2*)(lhb+p);
            const float2 h2 = *(const float2*)(hlb+p);
            const float2 d2 = *(const float2*)(hhb+p);
            float4 top, bot;
            top.x = (l2.x+a2.x+h2.x+d2.x)*0.5f;
            top.y = (l2.x+a2.x-h2.x-d2.x)*0.5f;
            bot.x = (l2.x-a2.x+h2.x-d2.x)*0.5f;
            bot.y = (l2.x-a2.x-h2.x+d2.x)*0.5f;
            top.z = (l2.y+a2.y+h2.y+d2.y)*0.5f;
            top.w = (l2.y+a2.y-h2.y-d2.y)*0.5f;
            bot.z = (l2.y-a2.y+h2.y-d2.y)*0.5f;
            bot.w = (l2.y-a2.y-h2.y+d2.y)*0.5f;
            *(float4*)&qs[r][xp*4]       = top;
            *(float4*)&qs[r][128 + xp*4] = bot;
        }
        // stage k: full-res rows 2yh, 2yh+1, cols 2*xh0..+127
        const size_t n0 = (size_t)(2*yh)*Wf + 2*xh0;
#pragma unroll
        for (int e = 0; e < 4; e++) {
            const int idx = t + e*256;
            const int r = idx >> 6, rem = idx & 63;
            const int row = rem >> 5, c4 = rem & 31;
            const float4 v = *(const float4*)(kb + (size_t)r*Nf + n0 + row*Wf + c4*4);
            *(float4*)&ks[r][row*128 + c4*4] = v;
        }
        __syncthreads();
#pragma unroll 8
        for (int nn = 0; nn < 256; nn++) {
            const float qv = qs[i][nn];
            const float kv = ks[j][nn];
            accS = fmaf(qv, kv, accS);
            if (j == 0) accQ = fmaf(qv, qv, accQ);
            if (i == 0) accK = fmaf(kv, kv, accK);
        }
        __syncthreads();
    }
    float* gp = gram + (size_t)(b*NHh + h)*288;
    atomicAdd(gp + i*16 + j, accS);
    if (j == 0) atomicAdd(gp + 256 + i, accQ);
    if (i == 0) atomicAdd(gp + 272 + j, accK);
}

// =====================================================================
// softmax + fold w_out
// =====================================================================
__global__ void attw_k(const float* __restrict__ gram,
                       const float* __restrict__ temp,
                       const float* __restrict__ wout,
                       float* __restrict__ weff)
{
    const int b = blockIdx.x;
    __shared__ float att[NHh][16][16];
    const int t = threadIdx.x;
    const float* gb = gram + (size_t)b*NHh*288;

    if (t < 128) {
        const int h = t >> 4, i = t & 15;
        const float* gp = gb + h*288;
        const float nq = fmaxf(sqrtf(gp[256+i]), 1e-12f);
        const float tv = temp[h];
        float logit[16];
        float mx = -1e30f;
#pragma unroll
        for (int j=0;j<16;j++) {
            const float nk = fmaxf(sqrtf(gp[272+j]), 1e-12f);
            const float l = gp[i*16+j] / (nq*nk) * tv;
            logit[j] = l;
            mx = fmaxf(mx, l);
        }
        float se = 0.f;
#pragma unroll
        for (int j=0;j<16;j++) { const float e = __expf(logit[j]-mx); logit[j]=e; se+=e; }
        const float inv = 1.f/se;
#pragma unroll
        for (int j=0;j<16;j++) att[h][i][j] = logit[j]*inv;
    }
    __syncthreads();

    float* wb = weff + (size_t)b*Cc*Cc;
    for (int idx = t; idx < Cc*Cc; idx += 256) {
        const int o = idx >> 7, cp = idx & 127;
        const int h = cp >> 4, j = cp & 15;
        float s = 0.f;
#pragma unroll
        for (int i=0;i<16;i++)
            s = fmaf(wout[(size_t)o*Cc + h*16 + i], att[h][i][j], s);
        wb[idx] = s;
    }
}

// =====================================================================
// host launch — exact R11/R15 graph
// =====================================================================
extern "C" void kernel_launch(void* const* d_in, const int* in_sizes, int n_in,
                              void* d_out, int out_size)
{
    const float* x      = (const float*)d_in[0];
    const float* prior  = (const float*)d_in[1];
    const float* w_lin  = (const float*)d_in[2];
    const float* b_lin  = (const float*)d_in[3];
    const float* w_qd   = (const float*)d_in[4];
    const float* w_kd   = (const float*)d_in[5];
    const float* w_vd   = (const float*)d_in[6];
    const float* gw_llr = (const float*)d_in[7];
    const float* gw_llh = (const float*)d_in[8];
    const float* gw_lh  = (const float*)d_in[9];
    const float* gw_hl  = (const float*)d_in[10];
    const float* gw_hh  = (const float*)d_in[11];
    const float* w_prior= (const float*)d_in[12];
    const float* b_prior= (const float*)d_in[13];
    const float* w_pw1  = (const float*)d_in[14];
    const float* b_pw1  = (const float*)d_in[15];
    const float* w_pw2  = (const float*)d_in[16];
    const float* b_pw2  = (const float*)d_in[17];
    const float* w_cat  = (const float*)d_in[18];
    const float* b_cat  = (const float*)d_in[19];
    const float* temper = (const float*)d_in[20];
    const float* w_out  = (const float*)d_in[21];
    const float* b_out  = (const float*)d_in[22];

    float *qkv, *qkvd, *hbuf, *masks, *qcat, *gram, *weff;
    cudaGetSymbolAddress((void**)&qkv,   g_qkv);
    cudaGetSymbolAddress((void**)&qkvd,  g_qkvd);
    cudaGetSymbolAddress((void**)&hbuf,  g_hbuf);
    cudaGetSymbolAddress((void**)&masks, g_masks);
    cudaGetSymbolAddress((void**)&qcat,  g_qcat);
    cudaGetSymbolAddress((void**)&gram,  g_gram);
    cudaGetSymbolAddress((void**)&weff,  g_weff);

    static cudaStream_t s1 = nullptr, s2 = nullptr;
    static cudaEvent_t eStart = nullptr, eQkv = nullptr, eKV = nullptr,
                       eM = nullptr, eDWT = nullptr, eG = nullptr,
                       eDual = nullptr, ePw2 = nullptr;
    if (s1 == nullptr) {
        cudaStreamCreateWithFlags(&s1, cudaStreamNonBlocking);
        cudaStreamCreateWithFlags(&s2, cudaStreamNonBlocking);
        cudaEventCreateWithFlags(&eStart, cudaEventDisableTiming);
        cudaEventCreateWithFlags(&eQkv,   cudaEventDisableTiming);
        cudaEventCreateWithFlags(&eKV,    cudaEventDisableTiming);
        cudaEventCreateWithFlags(&eM,     cudaEventDisableTiming);
        cudaEventCreateWithFlags(&eDWT,   cudaEventDisableTiming);
        cudaEventCreateWithFlags(&eG,     cudaEventDisableTiming);
        cudaEventCreateWithFlags(&eDual,  cudaEventDisableTiming);
        cudaEventCreateWithFlags(&ePw2,   cudaEventDisableTiming);
        cudaFuncSetAttribute(conv1x1_mma<0>, cudaFuncAttributeMaxDynamicSharedMemorySize, CONV_SMEM);
        cudaFuncSetAttribute(conv1x1_mma<1>, cudaFuncAttributeMaxDynamicSharedMemorySize, CONV_SMEM);
        cudaFuncSetAttribute(conv1x1_mma<2>, cudaFuncAttributeMaxDynamicSharedMemorySize, CONV_SMEM);
    }

    float* ll   = hbuf + 0*HB;
    float* lh   = hbuf + 1*HB;
    float* hl   = hbuf + 2*HB;
    float* hh   = hbuf + 3*HB;
    float* llrg = hbuf + 5*HB;
    float* llhg = hbuf + 6*HB;
    float* lhg  = hbuf + 7*HB;
    float* hlg  = hbuf + 8*HB;
    float* hhg  = hbuf + 9*HB;

    const size_t fullBS = (size_t)Cc*Nf;
    const size_t qkvBS  = (size_t)3*Cc*Nf;
    const size_t halfBS = (size_t)Cc*Nh2;
    const size_t mBS    = (size_t)5*Cc*Nh2;
    const size_t catBS  = (size_t)2*Cc*Nh2;

    const size_t xel = (size_t)in_sizes[0];
    const size_t pel = (size_t)in_sizes[1];

    // fork side streams
    cudaEventRecord(eStart, 0);
    cudaStreamWaitEvent(s2, eStart, 0);
    cudaStreamWaitEvent(s1, eStart, 0);

    // s1: independent work first
    if ((size_t)out_size >= xel + pel) {
        cudaMemcpyAsync((float*)d_out + xel, prior, pel*sizeof(float),
                        cudaMemcpyDeviceToDevice, s1);
    }
    cudaMemsetAsync(gram, 0, (size_t)Bq*NHh*288*sizeof(float), s1);

    // s2: masks = sigmoid(conv1x1(prior))
    conv1x1_mma<1><<<dim3(Nh2/128, 5, Bq), 256, CONV_SMEM, s2>>>(
        prior, w_prior, b_prior, masks, nullptr, Cc, Nh2, halfBS, mBS, 0, 0);
    cudaEventRecord(eM, s2);

    // 0: qkv = conv1x1(x, w_lin) + b_lin
    conv1x1_mma<0><<<dim3(Nf/128, 3, Bq), 256, CONV_SMEM>>>(
        x, w_lin, b_lin, qkv, nullptr, Cc, Nf, fullBS, qkvBS, 0, 0);
    cudaEventRecord(eQkv, 0);

    // s1: depthwise 3x3 on k,v (2 rows/thread)
    cudaStreamWaitEvent(s1, eQkv, 0);
    dwconv3_k<<<dim3(Wf/128, Hf/16, Bq*2*Cc), dim3(32,8), 0, s1>>>(qkv, w_kd, w_vd, qkvd);
    cudaEventRecord(eKV, s1);

    // 0: fused dwconv(q)+DWT (2 half-rows/thread)
    dwconv_dwt_k<<<dim3(2, Hh/16, Bq*Cc), dim3(32,8)>>>(qkv, w_qd, ll, lh, hl, hh);
    cudaEventRecord(eDWT, 0);

    dim3 gg(1, Hh/8, Bq*Cc), bg(32,8);

    // s2: single-stage gated convs with mask premultiply (masks already on s2)
    cudaStreamWaitEvent(s2, eDWT, 0);
    gated_s<3,5><<<gg, bg, 0, s2>>>(lh, gw_lh, masks, 1*Cc, lhg);
    gated_s<5,3><<<gg, bg, 0, s2>>>(hl, gw_hl, masks, 2*Cc, hlg);
    gated_s<3,3><<<gg, bg, 0, s2>>>(hh, gw_hh, masks, 3*Cc, hhg);
    cudaEventRecord(eG, s2);

    // 0: dual gated chain (llr+llh)
    gated2_dual_k<<<gg, bg>>>(ll, gw_llr, gw_llh, llrg, llhg);
    cudaEventRecord(eDual, 0);

    // s1: pw2 — concurrent with pw1 on 0
    cudaStreamWaitEvent(s1, eDual, 0);
    cudaStreamWaitEvent(s1, eM, 0);
    conv1x1_mma<2><<<dim3(Nh2/128, 1, Bq), 256, CONV_SMEM, s1>>>(
        llhg, w_pw2, b_pw2, qcat + (size_t)Cc*Nh2, masks + (size_t)4*Cc*Nh2, Cc, Nh2,
        halfBS, catBS, 0, mBS);
    cudaEventRecord(ePw2, s1);

    // 0: pw1
    cudaStreamWaitEvent(0, eM, 0);
    conv1x1_mma<2><<<dim3(Nh2/128, 1, Bq), 256, CONV_SMEM>>>(
        llrg, w_pw1, b_pw1, qcat, masks, Cc, Nh2, halfBS, catBS, 0, mBS);

    // 0: q_ll = conv1x1(cat, w_cat) + b_cat -> ll buffer
    cudaStreamWaitEvent(0, ePw2, 0);
    conv1x1_mma<0><<<dim3(Nh2/128, 1, Bq), 256, CONV_SMEM>>>(
        qcat, w_cat, b_cat, ll, nullptr, 2*Cc, Nh2, catBS, halfBS, 0, 0);

    // joins before fused gram
    cudaStreamWaitEvent(0, eG, 0);
    cudaStreamWaitEvent(0, eKV, 0);

    // 0: fused IDWT+gram, softmax-fold, final conv
    gram2_k<<<dim3(256/G2_T, NHh, Bq), 256>>>(ll, lhg, hlg, hhg, qkvd, gram);
    attw_k<<<Bq, 256>>>(gram, temper, w_out, weff);
    conv1x1_mma<0><<<dim3(Nf/128, 1, Bq), 256, CONV_SMEM>>>(
        qkvd + (size_t)2*Cc*Nf, weff, b_out, (float*)d_out, nullptr, Cc, Nf,
        qkvBS, fullBS, (size_t)Cc*Cc, 0);
}

// round 17
// speedup vs baseline: 1.0514x; 1.0116x over previous
#include <cuda_runtime.h>
#include <cuda_bf16.h>
#include <cstdint>
#include <math.h>

// ---------------- problem constants ----------------
#define Bq   2
#define Cc   128
#define Hf   256
#define Wf   256
#define Nf   (Hf*Wf)      // 65536
#define Hh   128
#define Wh   128
#define Nh2  (Hh*Wh)      // 16384
#define NHh  8
#define HD   16

#define HB   ((size_t)Bq*Cc*Nh2)

// ---------------- device scratch ----------------
__device__ float g_qkv [(size_t)Bq*3*Cc*Nf];
__device__ float g_qkvd[(size_t)Bq*3*Cc*Nf];
__device__ float g_hbuf[10*((size_t)Bq*Cc*Nh2)];
__device__ float g_masks[(size_t)Bq*5*Cc*Nh2];
__device__ float g_qcat [(size_t)Bq*2*Cc*Nh2];
__device__ float g_gram [Bq*NHh*288];
__device__ float g_weff [Bq*Cc*Cc];

__device__ __forceinline__ float sigm(float v) { return 1.f/(1.f+__expf(-v)); }

// =====================================================================
// tf32 helpers
// =====================================================================
__device__ __forceinline__ uint32_t f2tf32(float f) {
    uint32_t r;
    asm("cvt.rna.tf32.f32 %0, %1;" : "=r"(r) : "f"(f));
    return r;
}
__device__ __forceinline__ void mma_tf32(float c[4], const uint32_t a[4], const uint32_t b[2]) {
    asm volatile(
        "mma.sync.aligned.m16n8k8.row.col.f32.tf32.tf32.f32 "
        "{%0,%1,%2,%3}, {%4,%5,%6,%7}, {%8,%9}, {%0,%1,%2,%3};"
        : "+f"(c[0]), "+f"(c[1]), "+f"(c[2]), "+f"(c[3])
        : "r"(a[0]), "r"(a[1]), "r"(a[2]), "r"(a[3]), "r"(b[0]), "r"(b[1]));
}

// =====================================================================
// conv1x1 tf32 GEMM — double-buffered A&B, one sync per 32-K stage (R11)
// =====================================================================
#define A_STR 36
#define B_STR 132
#define AWRD (128*A_STR)
#define BWRD (32*B_STR)
#define CONV_SMEM ((2*AWRD + 2*BWRD)*4)   // 70656 bytes

template<int EPI>
__global__ void __launch_bounds__(256, 2) conv1x1_mma(
    const float* __restrict__ in, const float* __restrict__ w,
    const float* __restrict__ bias, float* __restrict__ out,
    const float* __restrict__ mask,
    int Cin, int P,
    size_t inBS, size_t outBS, size_t wBS, size_t maskBS)
{
    extern __shared__ uint32_t sdyn[];
    uint32_t* const Asb[2] = { sdyn, sdyn + AWRD };
    uint32_t* const Bsb[2] = { sdyn + 2*AWRD, sdyn + 2*AWRD + BWRD };

    const int b = blockIdx.z;
    in  += (size_t)b * inBS;
    out += (size_t)b * outBS;
    w   += (size_t)b * wBS;
    if (EPI == 2) mask += (size_t)b * maskBS;

    const int p0 = blockIdx.x * 128;
    const int o0 = blockIdx.y * 128;

    const int t = threadIdx.x;
    const int lane = t & 31;
    const int wrp  = t >> 5;
    const int wm   = wrp & 3;
    const int wn   = wrp >> 2;
    const int gid  = lane >> 2;
    const int tig  = lane & 3;

    int aOff[4], bOff[4];
#pragma unroll
    for (int i = 0; i < 4; i++) {
        const int slot = t + i * 256;
        aOff[i] = (slot >> 3) * A_STR + (slot & 7) * 4;
        bOff[i] = (slot >> 5) * B_STR + (slot & 31) * 4;
    }

    float acc[2][8][4];
#pragma unroll
    for (int i = 0; i < 2; i++)
#pragma unroll
        for (int j = 0; j < 8; j++)
#pragma unroll
            for (int r = 0; r < 4; r++) acc[i][j][r] = 0.f;

    const int nStages = Cin >> 5;

    float4 aPre[4], bPre[4];
    auto loadStage = [&](int s) {
        const float* wb = w + (size_t)o0 * Cin + (s << 5);
        const float* ib = in + (size_t)(s << 5) * P + p0;
#pragma unroll
        for (int i = 0; i < 4; i++) {
            const int slot = t + i * 256;
            aPre[i] = *(const float4*)(wb + (size_t)(slot >> 3) * Cin + (slot & 7) * 4);
            bPre[i] = *(const float4*)(ib + (size_t)(slot >> 5) * P + (slot & 31) * 4);
        }
    };
    auto stsStage = [&](int buf) {
        uint32_t* As = Asb[buf];
        uint32_t* Bs = Bsb[buf];
#pragma unroll
        for (int i = 0; i < 4; i++) {
            uint4 ua, ub;
            ua.x = f2tf32(aPre[i].x); ua.y = f2tf32(aPre[i].y);
            ua.z = f2tf32(aPre[i].z); ua.w = f2tf32(aPre[i].w);
            ub.x = f2tf32(bPre[i].x); ub.y = f2tf32(bPre[i].y);
            ub.z = f2tf32(bPre[i].z); ub.w = f2tf32(bPre[i].w);
            *(uint4*)(As + aOff[i]) = ua;
            *(uint4*)(Bs + bOff[i]) = ub;
        }
    };

    loadStage(0);
    stsStage(0);

    for (int stage = 0; stage < nStages; stage++) {
        const int buf = stage & 1;
        if (stage + 1 < nStages) loadStage(stage + 1);
        __syncthreads();

        const uint32_t* As = Asb[buf];
        const uint32_t* Bs = Bsb[buf];
#pragma unroll
        for (int k0 = 0; k0 < 32; k0 += 8) {
            uint32_t af[2][4];
#pragma unroll
            for (int tm = 0; tm < 2; tm++) {
                const int rb = wm * 32 + tm * 16;
                af[tm][0] = As[(rb + gid    ) * A_STR + k0 + tig    ];
                af[tm][1] = As[(rb + gid + 8) * A_STR + k0 + tig    ];
                af[tm][2] = As[(rb + gid    ) * A_STR + k0 + tig + 4];
                af[tm][3] = As[(rb + gid + 8) * A_STR + k0 + tig + 4];
            }
#pragma unroll
            for (int tn = 0; tn < 8; tn++) {
                uint32_t bf[2];
                const int col = wn * 64 + tn * 8 + gid;
                bf[0] = Bs[(k0 + tig    ) * B_STR + col];
                bf[1] = Bs[(k0 + tig + 4) * B_STR + col];
#pragma unroll
                for (int tm = 0; tm < 2; tm++)
                    mma_tf32(acc[tm][tn], af[tm], bf);
            }
        }
        if (stage + 1 < nStages) stsStage((stage + 1) & 1);
    }

#pragma unroll
    for (int tm = 0; tm < 2; tm++) {
        const int oA = o0 + wm * 32 + tm * 16 + gid;
        const int oB = oA + 8;
        const float bvA = __ldg(bias + oA);
        const float bvB = __ldg(bias + oB);
#pragma unroll
        for (int tn = 0; tn < 8; tn++) {
            const int p = p0 + wn * 64 + tn * 8 + tig * 2;
            float v0 = acc[tm][tn][0] + bvA;
            float v1 = acc[tm][tn][1] + bvA;
            float v2 = acc[tm][tn][2] + bvB;
            float v3 = acc[tm][tn][3] + bvB;
            if (EPI == 1) {
                v0 = sigm(v0); v1 = sigm(v1); v2 = sigm(v2); v3 = sigm(v3);
            }
            if (EPI == 2) {
                const float2 iA = *(const float2*)(in + (size_t)oA * P + p);
                const float2 iB = *(const float2*)(in + (size_t)oB * P + p);
                const float2 mA = *(const float2*)(mask + (size_t)oA * P + p);
                const float2 mB = *(const float2*)(mask + (size_t)oB * P + p);
                v0 = iA.x + v0 * mA.x; v1 = iA.y + v1 * mA.y;
                v2 = iB.x + v2 * mB.x; v3 = iB.y + v3 * mB.y;
            }
            *(float2*)(out + (size_t)oA * P + p) = make_float2(v0, v1);
            *(float2*)(out + (size_t)oB * P + p) = make_float2(v2, v3);
        }
    }
}

// =====================================================================
// depthwise 3x3 on k,v channels — 2 rows x 4 cols per thread (R15)
// =====================================================================
__global__ void __launch_bounds__(256) dwconv3_k(
    const float* __restrict__ in, const float* __restrict__ wk,
    const float* __restrict__ wv, float* __restrict__ out)
{
    const int zc2 = blockIdx.z;
    const int b   = zc2 / (2*Cc);
    const int ch2 = zc2 % (2*Cc);
    const int cm  = ch2 % Cc;
    const float* ws = (ch2 < Cc) ? wk : wv;
    float wgt[9];
#pragma unroll
    for (int i=0;i<9;i++) wgt[i] = __ldg(ws + cm*9 + i);

    const size_t off = ((size_t)b*3*Cc + Cc + ch2)*Nf;
    const float* ip = in  + off;
    float*       op = out + off;

    const int x0 = (blockIdx.x*32 + threadIdx.x)*4;
    const int y0 = (blockIdx.y*8  + threadIdx.y)*2;

    float r[4][6];
#pragma unroll
    for (int dy=0; dy<4; dy++) {
        const int yy = y0 + dy - 1;
        const bool rv = (unsigned)yy < (unsigned)Hf;
        const float* rp = ip + (size_t)yy*Wf;
        if (rv) {
            const float4 m = *(const float4*)(rp + x0);
            r[dy][1]=m.x; r[dy][2]=m.y; r[dy][3]=m.z; r[dy][4]=m.w;
            r[dy][0] = (x0 > 0)      ? __ldg(rp + x0 - 1) : 0.f;
            r[dy][5] = (x0 + 4 < Wf) ? __ldg(rp + x0 + 4) : 0.f;
        } else {
#pragma unroll
            for (int j=0;j<6;j++) r[dy][j] = 0.f;
        }
    }
    float o[2][4];
#pragma unroll
    for (int qy=0; qy<2; qy++)
#pragma unroll
        for (int j=0; j<4; j++) o[qy][j] = 0.f;
#pragma unroll
    for (int qy=0; qy<2; qy++)
#pragma unroll
        for (int dy=0; dy<3; dy++)
#pragma unroll
            for (int dx=0; dx<3; dx++) {
                const float wv_ = wgt[dy*3+dx];
#pragma unroll
                for (int j=0; j<4; j++)
                    o[qy][j] = fmaf(r[qy+dy][j+dx], wv_, o[qy][j]);
            }
    *(float4*)(op + (size_t)y0*Wf + x0)     = make_float4(o[0][0],o[0][1],o[0][2],o[0][3]);
    *(float4*)(op + (size_t)(y0+1)*Wf + x0) = make_float4(o[1][0],o[1][1],o[1][2],o[1][3]);
}

// =====================================================================
// fused dwconv3(q) + Haar DWT — 2 half-rows x 2 half-px per thread (R16)
// =====================================================================
__global__ void __launch_bounds__(256) dwconv_dwt_k(
    const float* __restrict__ in, const float* __restrict__ wq,
    float* __restrict__ ll, float* __restrict__ lh,
    float* __restrict__ hl, float* __restrict__ hh)
{
    const int zc = blockIdx.z;               // b*C + ch
    const int b = zc / Cc, ch = zc % Cc;
    float wgt[9];
#pragma unroll
    for (int i=0;i<9;i++) wgt[i] = __ldg(wq + ch*9 + i);

    const float* ip = in + ((size_t)b*3*Cc + ch)*Nf;
    const size_t ho = (size_t)zc*Nh2;

    const int xq  = blockIdx.x*32 + threadIdx.x;
    const int yh0 = (blockIdx.y*8 + threadIdx.y)*2;
    const int fx  = xq*4;

    float r[6][6];
#pragma unroll
    for (int dy=0; dy<6; dy++) {
        const int yy = 2*yh0 + dy - 1;
        const bool rv = (unsigned)yy < (unsigned)Hf;
        const float* rp = ip + (size_t)yy*Wf;
        if (rv) {
            const float4 m = *(const float4*)(rp + fx);
            r[dy][1]=m.x; r[dy][2]=m.y; r[dy][3]=m.z; r[dy][4]=m.w;
            r[dy][0] = (fx > 0)      ? __ldg(rp + fx - 1) : 0.f;
            r[dy][5] = (fx + 4 < Wf) ? __ldg(rp + fx + 4) : 0.f;
        } else {
#pragma unroll
            for (int j=0;j<6;j++) r[dy][j] = 0.f;
        }
    }
    float o[4][4];
#pragma unroll
    for (int qy=0; qy<4; qy++)
#pragma unroll
        for (int k=0; k<4; k++) {
            float s = 0.f;
#pragma unroll
            for (int ky=0; ky<3; ky++)
#pragma unroll
                for (int kx=0; kx<3; kx++)
                    s = fmaf(r[qy+ky][k+kx], wgt[ky*3+kx], s);
            o[qy][k] = s;
        }
#pragma unroll
    for (int hr=0; hr<2; hr++) {
        const size_t p = ho + (size_t)(yh0+hr)*Wh + xq*2;
        float2 vll, vlh, vhl, vhh;
        {
            const float a=o[2*hr][0], bb2=o[2*hr][1], c=o[2*hr+1][0], d=o[2*hr+1][1];
            vll.x=(a+bb2+c+d)*0.5f; vlh.x=(a+bb2-c-d)*0.5f;
            vhl.x=(a-bb2+c-d)*0.5f; vhh.x=(a-bb2-c+d)*0.5f;
        }
        {
            const float a=o[2*hr][2], bb2=o[2*hr][3], c=o[2*hr+1][2], d=o[2*hr+1][3];
            vll.y=(a+bb2+c+d)*0.5f; vlh.y=(a+bb2-c-d)*0.5f;
            vhl.y=(a-bb2+c-d)*0.5f; vhh.y=(a-bb2-c+d)*0.5f;
        }
        *(float2*)(ll+p) = vll;
        *(float2*)(lh+p) = vlh;
        *(float2*)(hl+p) = vhl;
        *(float2*)(hh+p) = vhh;
    }
}

// =====================================================================
// smem-tiled single-stage gated conv + mask premultiply
// =====================================================================
template<int KH,int KW>
__global__ void __launch_bounds__(256) gated_s(
    const float* __restrict__ in, const float* __restrict__ w,
    const float* __restrict__ masks, int bandOff,
    float* __restrict__ out)
{
    constexpr int HALO_Y = KH/2, HALO_X = KW/2;
    constexpr int TR = 8 + KH - 1;
    constexpr int TC = 128 + KW - 1;
    __shared__ float sm[TR][TC];
    __shared__ float wsm[2][KH*KW];

    const int zc = blockIdx.z;
    const int b  = zc / Cc;
    const int ch = zc % Cc;
    const int t  = threadIdx.y*32 + threadIdx.x;
    if (t < 2*KH*KW) {
        const int br = t / (KH*KW), i = t % (KH*KW);
        wsm[br][i] = __ldg(w + (size_t)br*Cc*KH*KW + (size_t)ch*KH*KW + i);
    }

    const float* ip = in + (size_t)zc*Nh2;
    const float* mp = masks + ((size_t)b*5*Cc + bandOff + ch)*Nh2;
    const int Y0 = blockIdx.y*8;

    for (int idx = t; idx < TR*TC; idx += 256) {
        const int r = idx / TC, c = idx % TC;
        const int gy = Y0 - HALO_Y + r, gx = c - HALO_X;
        sm[r][c] = ((unsigned)gy < (unsigned)Hh && (unsigned)gx < (unsigned)Wh)
                   ? __ldg(ip + (size_t)gy*Wh + gx) : 0.f;
    }
    __syncthreads();

    const int ty = threadIdx.y;
    const int x0 = threadIdx.x*4;
    float s0[4] = {0,0,0,0}, s1[4] = {0,0,0,0};
#pragma unroll
    for (int ky=0; ky<KH; ky++) {
        float row[KW+3];
#pragma unroll
        for (int j=0; j<KW+3; j++) row[j] = sm[ty+ky][x0+j];
#pragma unroll
        for (int kx=0; kx<KW; kx++) {
            const float a0 = wsm[0][ky*KW+kx], a1 = wsm[1][ky*KW+kx];
#pragma unroll
            for (int j=0; j<4; j++) {
                s0[j] = fmaf(row[j+kx], a0, s0[j]);
                s1[j] = fmaf(row[j+kx], a1, s1[j]);
            }
        }
    }
    const float4 mv = *(const float4*)(mp + (size_t)(Y0+ty)*Wh + x0);
    float4 o;
    o.x = s0[0]*sigm(s1[0])*mv.x; o.y = s0[1]*sigm(s1[1])*mv.y;
    o.z = s0[2]*sigm(s1[2])*mv.z; o.w = s0[3]*sigm(s1[3])*mv.w;
    *(float4*)(out + (size_t)zc*Nh2 + (size_t)(Y0+ty)*Wh + x0) = o;
}

// =====================================================================
// fused dual 2-stage gated chains — 16-row tile (halo amortized)
// =====================================================================
__global__ void __launch_bounds__(256, 5) gated2_dual_k(
    const float* __restrict__ in,
    const float* __restrict__ wA, const float* __restrict__ wB,
    float* __restrict__ outA, float* __restrict__ outB)
{
    __shared__ float sm[20][132];     // rows Y0-2 .. Y0+17
    __shared__ float midA[18][132];   // rows Y0-1 .. Y0+16
    __shared__ float midB[18][132];
    __shared__ float wsm[8][9];

    const int zc = blockIdx.z;
    const int ch = zc % Cc;
    const int t  = threadIdx.y*32 + threadIdx.x;

    if (t < 72) {
        const int set = t / 9, i = t % 9;
        const float* base = (set < 4) ? wA : wB;
        const int s4 = set & 3;
        wsm[set][i] = __ldg(base + (size_t)s4*Cc*9 + (size_t)ch*9 + i);
    }

    const float* ip = in + (size_t)zc*Nh2;
    const int Y0 = blockIdx.y*16;

    for (int idx = t; idx < 20*132; idx += 256) {
        const int r = idx / 132, c = idx % 132;
        const int gy = Y0 - 2 + r, gx = c - 2;
        sm[r][c] = ((unsigned)gy < (unsigned)Hh && (unsigned)gx < (unsigned)Wh)
                   ? __ldg(ip + (size_t)gy*Wh + gx) : 0.f;
    }
    __syncthreads();

    for (int idx = t; idx < 18*130; idx += 256) {
        const int r = idx / 130, c = idx % 130;
        const int gy = Y0 - 1 + r, gx = c - 1;
        float a0=0, a1=0, b0=0, b1=0;
        if ((unsigned)gy < (unsigned)Hh && (unsigned)gx < (unsigned)Wh) {
#pragma unroll
            for (int ky=0; ky<3; ky++)
#pragma unroll
                for (int kx=0; kx<3; kx++) {
                    const float v = sm[r+ky][c+kx];
                    const int i = ky*3+kx;
                    a0 = fmaf(v, wsm[0][i], a0);
                    a1 = fmaf(v, wsm[1][i], a1);
                    b0 = fmaf(v, wsm[4][i], b0);
                    b1 = fmaf(v, wsm[5][i], b1);
                }
        }
        midA[r][c] = a0 * sigm(a1);
        midB[r][c] = b0 * sigm(b1);
    }
    __syncthreads();

    const int x0 = threadIdx.x*4;
#pragma unroll
    for (int half = 0; half < 2; half++) {
        const int ty = threadIdx.y + half*8;   // output row within tile 0..15
        float sA0[4]={0,0,0,0}, sA1[4]={0,0,0,0}, sB0[4]={0,0,0,0}, sB1[4]={0,0,0,0};
#pragma unroll
        for (int ky=0; ky<3; ky++) {
            float rA[6], rB[6];
#pragma unroll
            for (int j=0; j<6; j++) { rA[j] = midA[ty+ky][x0+j]; rB[j] = midB[ty+ky][x0+j]; }
#pragma unroll
            for (int kx=0; kx<3; kx++) {
                const int i = ky*3+kx;
                const float a2_0 = wsm[2][i], a2_1 = wsm[3][i];
                const float b2_0 = wsm[6][i], b2_1 = wsm[7][i];
#pragma unroll
                for (int j=0; j<4; j++) {
                    sA0[j] = fmaf(rA[j+kx], a2_0, sA0[j]);
                    sA1[j] = fmaf(rA[j+kx], a2_1, sA1[j]);
                    sB0[j] = fmaf(rB[j+kx], b2_0, sB0[j]);
                    sB1[j] = fmaf(rB[j+kx], b2_1, sB1[j]);
                }
            }
        }
        const size_t op = (size_t)zc*Nh2 + (size_t)(Y0+ty)*Wh + x0;
        float4 oA, oB;
        oA.x = sA0[0]*sigm(sA1[0]); oA.y = sA0[1]*sigm(sA1[1]);
        oA.z = sA0[2]*sigm(sA1[2]); oA.w = sA0[3]*sigm(sA1[3]);
        oB.x = sB0[0]*sigm(sB1[0]); oB.y = sB0[1]*sigm(sB1[1]);
        oB.z = sB0[2]*sigm(sB1[2]); oB.w = sB0[3]*sigm(sB1[3]);
        *(float4*)(outA + op) = oA;
        *(float4*)(outB + op) = oB;
    }
}

// =====================================================================
// fused IDWT + gram — float2 band loads, float4 qs stores (R16)
// =====================================================================
#define G2_T 8
#define QS_STR 260
__global__ void __launch_bounds__(256) gram2_k(
    const float* __restrict__ ll, const float* __restrict__ lh,
    const float* __restrict__ hl, const float* __restrict__ hh,
    const float* __restrict__ kall, float* __restrict__ gram)
{
    const int h = blockIdx.y, b = blockIdx.z;
    const size_t cb = ((size_t)b*Cc + h*HD)*Nh2;
    const float* llb = ll + cb;
    const float* lhb = lh + cb;
    const float* hlb = hl + cb;
    const float* hhb = hh + cb;
    const float* kb  = kall + (size_t)b*3*Cc*Nf + (size_t)Cc*Nf + (size_t)h*HD*Nf;

    __shared__ float qs[16][QS_STR];
    __shared__ float ks[16][QS_STR];

    const int t = threadIdx.x;
    const int i = t >> 4, j = t & 15;
    float accS = 0.f, accQ = 0.f, accK = 0.f;

    for (int tt = 0; tt < G2_T; tt++) {
        const int tileId = blockIdx.x * G2_T + tt;
        const int yh  = tileId >> 1;
        const int xh0 = (tileId & 1) * 64;

#pragma unroll
        for (int e = 0; e < 2; e++) {
            const int idx = t + e*256;
            const int r = idx >> 5, xp = idx & 31;
            const size_t p = (size_t)r*Nh2 + (size_t)yh*Wh + xh0 + xp*2;
            const float2 l2 = *(const float2*)(llb+p);
            const float2 a2 = *(const float2*)(lhb+p);
            const float2 h2 = *(const float2*)(hlb+p);
            const float2 d2 = *(const float2*)(hhb+p);
            float4 top, bot;
            top.x = (l2.x+a2.x+h2.x+d2.x)*0.5f;
            top.y = (l2.x+a2.x-h2.x-d2.x)*0.5f;
            bot.x = (l2.x-a2.x+h2.x-d2.x)*0.5f;
            bot.y = (l2.x-a2.x-h2.x+d2.x)*0.5f;
            top.z = (l2.y+a2.y+h2.y+d2.y)*0.5f;
            top.w = (l2.y+a2.y-h2.y-d2.y)*0.5f;
            bot.z = (l2.y-a2.y+h2.y-d2.y)*0.5f;
            bot.w = (l2.y-a2.y-h2.y+d2.y)*0.5f;
            *(float4*)&qs[r][xp*4]       = top;
            *(float4*)&qs[r][128 + xp*4] = bot;
        }
        const size_t n0 = (size_t)(2*yh)*Wf + 2*xh0;
#pragma unroll
        for (int e = 0; e < 4; e++) {
            const int idx = t + e*256;
            const int r = idx >> 6, rem = idx & 63;
            const int row = rem >> 5, c4 = rem & 31;
            const float4 v = *(const float4*)(kb + (size_t)r*Nf + n0 + row*Wf + c4*4);
            *(float4*)&ks[r][row*128 + c4*4] = v;
        }
        __syncthreads();
#pragma unroll 8
        for (int nn = 0; nn < 256; nn++) {
            const float qv = qs[i][nn];
            const float kv = ks[j][nn];
            accS = fmaf(qv, kv, accS);
            if (j == 0) accQ = fmaf(qv, qv, accQ);
            if (i == 0) accK = fmaf(kv, kv, accK);
        }
        __syncthreads();
    }
    float* gp = gram + (size_t)(b*NHh + h)*288;
    atomicAdd(gp + i*16 + j, accS);
    if (j == 0) atomicAdd(gp + 256 + i, accQ);
    if (i == 0) atomicAdd(gp + 272 + j, accK);
}

// =====================================================================
// softmax + fold w_out
// =====================================================================
__global__ void attw_k(const float* __restrict__ gram,
                       const float* __restrict__ temp,
                       const float* __restrict__ wout,
                       float* __restrict__ weff)
{
    const int b = blockIdx.x;
    __shared__ float att[NHh][16][16];
    const int t = threadIdx.x;
    const float* gb = gram + (size_t)b*NHh*288;

    if (t < 128) {
        const int h = t >> 4, i = t & 15;
        const float* gp = gb + h*288;
        const float nq = fmaxf(sqrtf(gp[256+i]), 1e-12f);
        const float tv = temp[h];
        float logit[16];
        float mx = -1e30f;
#pragma unroll
        for (int j=0;j<16;j++) {
            const float nk = fmaxf(sqrtf(gp[272+j]), 1e-12f);
            const float l = gp[i*16+j] / (nq*nk) * tv;
            logit[j] = l;
            mx = fmaxf(mx, l);
        }
        float se = 0.f;
#pragma unroll
        for (int j=0;j<16;j++) { const float e = __expf(logit[j]-mx); logit[j]=e; se+=e; }
        const float inv = 1.f/se;
#pragma unroll
        for (int j=0;j<16;j++) att[h][i][j] = logit[j]*inv;
    }
    __syncthreads();

    float* wb = weff + (size_t)b*Cc*Cc;
    for (int idx = t; idx < Cc*Cc; idx += 256) {
        const int o = idx >> 7, cp = idx & 127;
        const int h = cp >> 4, j = cp & 15;
        float s = 0.f;
#pragma unroll
        for (int i=0;i<16;i++)
            s = fmaf(wout[(size_t)o*Cc + h*16 + i], att[h][i][j], s);
        wb[idx] = s;
    }
}

// =====================================================================
// host launch — exact R11/R15/R16 graph
// =====================================================================
extern "C" void kernel_launch(void* const* d_in, const int* in_sizes, int n_in,
                              void* d_out, int out_size)
{
    const float* x      = (const float*)d_in[0];
    const float* prior  = (const float*)d_in[1];
    const float* w_lin  = (const float*)d_in[2];
    const float* b_lin  = (const float*)d_in[3];
    const float* w_qd   = (const float*)d_in[4];
    const float* w_kd   = (const float*)d_in[5];
    const float* w_vd   = (const float*)d_in[6];
    const float* gw_llr = (const float*)d_in[7];
    const float* gw_llh = (const float*)d_in[8];
    const float* gw_lh  = (const float*)d_in[9];
    const float* gw_hl  = (const float*)d_in[10];
    const float* gw_hh  = (const float*)d_in[11];
    const float* w_prior= (const float*)d_in[12];
    const float* b_prior= (const float*)d_in[13];
    const float* w_pw1  = (const float*)d_in[14];
    const float* b_pw1  = (const float*)d_in[15];
    const float* w_pw2  = (const float*)d_in[16];
    const float* b_pw2  = (const float*)d_in[17];
    const float* w_cat  = (const float*)d_in[18];
    const float* b_cat  = (const float*)d_in[19];
    const float* temper = (const float*)d_in[20];
    const float* w_out  = (const float*)d_in[21];
    const float* b_out  = (const float*)d_in[22];

    float *qkv, *qkvd, *hbuf, *masks, *qcat, *gram, *weff;
    cudaGetSymbolAddress((void**)&qkv,   g_qkv);
    cudaGetSymbolAddress((void**)&qkvd,  g_qkvd);
    cudaGetSymbolAddress((void**)&hbuf,  g_hbuf);
    cudaGetSymbolAddress((void**)&masks, g_masks);
    cudaGetSymbolAddress((void**)&qcat,  g_qcat);
    cudaGetSymbolAddress((void**)&gram,  g_gram);
    cudaGetSymbolAddress((void**)&weff,  g_weff);

    static cudaStream_t s1 = nullptr, s2 = nullptr;
    static cudaEvent_t eStart = nullptr, eQkv = nullptr, eKV = nullptr,
                       eM = nullptr, eDWT = nullptr, eG = nullptr,
                       eDual = nullptr, ePw2 = nullptr;
    if (s1 == nullptr) {
        cudaStreamCreateWithFlags(&s1, cudaStreamNonBlocking);
        cudaStreamCreateWithFlags(&s2, cudaStreamNonBlocking);
        cudaEventCreateWithFlags(&eStart, cudaEventDisableTiming);
        cudaEventCreateWithFlags(&eQkv,   cudaEventDisableTiming);
        cudaEventCreateWithFlags(&eKV,    cudaEventDisableTiming);
        cudaEventCreateWithFlags(&eM,     cudaEventDisableTiming);
        cudaEventCreateWithFlags(&eDWT,   cudaEventDisableTiming);
        cudaEventCreateWithFlags(&eG,     cudaEventDisableTiming);
        cudaEventCreateWithFlags(&eDual,  cudaEventDisableTiming);
        cudaEventCreateWithFlags(&ePw2,   cudaEventDisableTiming);
        cudaFuncSetAttribute(conv1x1_mma<0>, cudaFuncAttributeMaxDynamicSharedMemorySize, CONV_SMEM);
        cudaFuncSetAttribute(conv1x1_mma<1>, cudaFuncAttributeMaxDynamicSharedMemorySize, CONV_SMEM);
        cudaFuncSetAttribute(conv1x1_mma<2>, cudaFuncAttributeMaxDynamicSharedMemorySize, CONV_SMEM);
    }

    float* ll   = hbuf + 0*HB;
    float* lh   = hbuf + 1*HB;
    float* hl   = hbuf + 2*HB;
    float* hh   = hbuf + 3*HB;
    float* llrg = hbuf + 5*HB;
    float* llhg = hbuf + 6*HB;
    float* lhg  = hbuf + 7*HB;
    float* hlg  = hbuf + 8*HB;
    float* hhg  = hbuf + 9*HB;

    const size_t fullBS = (size_t)Cc*Nf;
    const size_t qkvBS  = (size_t)3*Cc*Nf;
    const size_t halfBS = (size_t)Cc*Nh2;
    const size_t mBS    = (size_t)5*Cc*Nh2;
    const size_t catBS  = (size_t)2*Cc*Nh2;

    const size_t xel = (size_t)in_sizes[0];
    const size_t pel = (size_t)in_sizes[1];

    // fork side streams
    cudaEventRecord(eStart, 0);
    cudaStreamWaitEvent(s2, eStart, 0);
    cudaStreamWaitEvent(s1, eStart, 0);

    // s1: independent work first
    if ((size_t)out_size >= xel + pel) {
        cudaMemcpyAsync((float*)d_out + xel, prior, pel*sizeof(float),
                        cudaMemcpyDeviceToDevice, s1);
    }
    cudaMemsetAsync(gram, 0, (size_t)Bq*NHh*288*sizeof(float), s1);

    // s2: masks = sigmoid(conv1x1(prior))
    conv1x1_mma<1><<<dim3(Nh2/128, 5, Bq), 256, CONV_SMEM, s2>>>(
        prior, w_prior, b_prior, masks, nullptr, Cc, Nh2, halfBS, mBS, 0, 0);
    cudaEventRecord(eM, s2);

    // 0: qkv = conv1x1(x, w_lin) + b_lin
    conv1x1_mma<0><<<dim3(Nf/128, 3, Bq), 256, CONV_SMEM>>>(
        x, w_lin, b_lin, qkv, nullptr, Cc, Nf, fullBS, qkvBS, 0, 0);
    cudaEventRecord(eQkv, 0);

    // s1: depthwise 3x3 on k,v (2 rows/thread)
    cudaStreamWaitEvent(s1, eQkv, 0);
    dwconv3_k<<<dim3(Wf/128, Hf/16, Bq*2*Cc), dim3(32,8), 0, s1>>>(qkv, w_kd, w_vd, qkvd);
    cudaEventRecord(eKV, s1);

    // 0: fused dwconv(q)+DWT (2 half-rows/thread)
    dwconv_dwt_k<<<dim3(2, Hh/16, Bq*Cc), dim3(32,8)>>>(qkv, w_qd, ll, lh, hl, hh);
    cudaEventRecord(eDWT, 0);

    dim3 gg(1, Hh/8, Bq*Cc), bg(32,8);
    dim3 gg16(1, Hh/16, Bq*Cc);

    // s2: single-stage gated convs with mask premultiply (masks already on s2)
    cudaStreamWaitEvent(s2, eDWT, 0);
    gated_s<3,5><<<gg, bg, 0, s2>>>(lh, gw_lh, masks, 1*Cc, lhg);
    gated_s<5,3><<<gg, bg, 0, s2>>>(hl, gw_hl, masks, 2*Cc, hlg);
    gated_s<3,3><<<gg, bg, 0, s2>>>(hh, gw_hh, masks, 3*Cc, hhg);
    cudaEventRecord(eG, s2);

    // 0: dual gated chain (llr+llh) — 16-row tiles
    gated2_dual_k<<<gg16, bg>>>(ll, gw_llr, gw_llh, llrg, llhg);
    cudaEventRecord(eDual, 0);

    // s1: pw2 — concurrent with pw1 on 0
    cudaStreamWaitEvent(s1, eDual, 0);
    cudaStreamWaitEvent(s1, eM, 0);
    conv1x1_mma<2><<<dim3(Nh2/128, 1, Bq), 256, CONV_SMEM, s1>>>(
        llhg, w_pw2, b_pw2, qcat + (size_t)Cc*Nh2, masks + (size_t)4*Cc*Nh2, Cc, Nh2,
        halfBS, catBS, 0, mBS);
    cudaEventRecord(ePw2, s1);

    // 0: pw1
    cudaStreamWaitEvent(0, eM, 0);
    conv1x1_mma<2><<<dim3(Nh2/128, 1, Bq), 256, CONV_SMEM>>>(
        llrg, w_pw1, b_pw1, qcat, masks, Cc, Nh2, halfBS, catBS, 0, mBS);

    // 0: q_ll = conv1x1(cat, w_cat) + b_cat -> ll buffer
    cudaStreamWaitEvent(0, ePw2, 0);
    conv1x1_mma<0><<<dim3(Nh2/128, 1, Bq), 256, CONV_SMEM>>>(
        qcat, w_cat, b_cat, ll, nullptr, 2*Cc, Nh2, catBS, halfBS, 0, 0);

    // joins before fused gram
    cudaStreamWaitEvent(0, eG, 0);
    cudaStreamWaitEvent(0, eKV, 0);

    // 0: fused IDWT+gram, softmax-fold, final conv
    gram2_k<<<dim3(256/G2_T, NHh, Bq), 256>>>(ll, lhg, hlg, hhg, qkvd, gram);
    attw_k<<<Bq, 256>>>(gram, temper, w_out, weff);
    conv1x1_mma<0><<<dim3(Nf/128, 1, Bq), 256, CONV_SMEM>>>(
        qkvd + (size_t)2*Cc*Nf, weff, b_out, (float*)d_out, nullptr, Cc, Nf,
        qkvBS, fullBS, (size_t)Cc*Cc, 0);
}